// round 5
// baseline (speedup 1.0000x reference)
#include <cuda_runtime.h>

#define Bq 512
#define Tq 32
#define Nq 16384   // Tq*Bq, power of two: n = t*512 + b

// ---------------- scratch (static device arrays; no runtime alloc) ----------------
__device__ float g_xT[280 * Nq];    // [i*10+k][n] transposed local_inputs
__device__ float g_eT[4 * Nq];      // [i][n] transposed extras
__device__ float g_con[3000 * Nq];  // [k*300+j][n]
__device__ float g_con1[3000 * Nq]; // [k*300+j][n]
__device__ float g_ht[300 * Nq];    // [j][n]
__device__ float g_sm[Tq * 10 * Bq];// [t][r][c] softmaxed wdyn
__device__ float g_qpart[3 * 10 * Nq];  // per-z partial of con1 . u
__device__ float g_wdpart[2 * 10 * Nq]; // per-z partial of relu(fc1) . F2
__device__ float g_u[300];          // fuse1 @ Wout
__device__ float g_v[17];           // ff^T @ Wout
__device__ float g_wA[10];          // softmax(DisM)
__device__ float g_c[2];            // biasf.Wout, bff.Wout
__device__ float g_wpT[600 * 300];  // wp transposed to [h][o]

// ---------------- helpers ----------------
__device__ __forceinline__ float sigm(float x) {
    float e = __expf(-x);
    return __fdividef(1.f, 1.f + e);
}
__device__ __forceinline__ float tanh_(float x) {
    float e = __expf(-2.f * fabsf(x));
    float t = __fdividef(1.f - e, 1.f + e);
    return copysignf(t, x);
}
__device__ __forceinline__ void ffma2(unsigned long long& d, unsigned long long a,
                                      unsigned long long b) {
    asm("fma.rn.f32x2 %0, %1, %2, %0;" : "+l"(d) : "l"(a), "l"(b));
}

// ---------------- prep: tiny precomputations ----------------
__global__ void prep_small(const float* __restrict__ DisM, const float* __restrict__ fuse1,
                           const float* __restrict__ ff, const float* __restrict__ biasf,
                           const float* __restrict__ bff, const float* __restrict__ Wout) {
    int tid = threadIdx.x;
    if (tid < 300) {
        float s = 0.f;
        for (int o = 0; o < 100; o++) s = fmaf(fuse1[tid * 100 + o], Wout[o], s);
        g_u[tid] = s;
    }
    if (tid < 17) {
        float s = 0.f;
        for (int o = 0; o < 100; o++) s = fmaf(ff[o * 17 + tid], Wout[o], s);
        g_v[tid] = s;
    }
    if (tid == 300) {
        float s = 0.f;
        for (int o = 0; o < 100; o++) s = fmaf(biasf[o], Wout[o], s);
        g_c[0] = s;
    }
    if (tid == 301) {
        float s = 0.f;
        for (int o = 0; o < 100; o++) s = fmaf(bff[o], Wout[o], s);
        g_c[1] = s;
    }
    if (tid == 302) {
        float m = DisM[0];
        for (int k = 1; k < 10; k++) m = fmaxf(m, DisM[k]);
        float e[10], d = 0.f;
        for (int k = 0; k < 10; k++) { e[k] = __expf(DisM[k] - m); d += e[k]; }
        for (int k = 0; k < 10; k++) g_wA[k] = e[k] / d;
    }
}

__global__ void prep_wpT(const float* __restrict__ wp) {
    int idx = blockIdx.x * 256 + threadIdx.x;
    if (idx < 600 * 300) {
        int h = idx / 300, o = idx - h * 300;
        g_wpT[idx] = wp[o * 600 + h];
    }
}

// ---------------- transpose inputs to [feature][n] layout ----------------
__global__ void transpose_kernel(const float* __restrict__ li, const float* __restrict__ ex) {
    int idx = blockIdx.x * 256 + threadIdx.x;
    const int total1 = 280 * Nq;
    if (idx < total1) {
        int row = idx >> 14, n = idx & (Nq - 1);
        int i = row / 10, kk = row - i * 10;
        int t = n >> 9, b = n & 511;
        g_xT[idx] = li[((b * Tq + t) * 28 + i) * 10 + kk];
    } else {
        int j = idx - total1;
        if (j < 4 * Nq) {
            int i = j >> 14, n = j & (Nq - 1);
            int t = n >> 9, b = n & 511;
            g_eT[j] = ex[(b * Tq + t) * 4 + i];
        }
    }
}

// ---------------- cells: per-neighbor zero-state LSTM cell (f gate unused) ----------------
__global__ __launch_bounds__(128) void cells_kernel(const float* __restrict__ Wih,
                                                    const float* __restrict__ b_ih,
                                                    const float* __restrict__ b_hh) {
    int n = blockIdx.x * 128 + threadIdx.x;
    int k = blockIdx.y;
    float s[11];
#pragma unroll
    for (int i = 0; i < 11; i++) s[i] = g_xT[(i * 10 + k) * Nq + n];
    const float* W = Wih + k * 13200;   // [1200][11]
    const float* bi = b_ih + k * 1200;
    const float* bh = b_hh + k * 1200;
    int outb = k * 300 * Nq + n;
    for (int j = 0; j < 300; j++) {
        float gi = bi[j] + bh[j];
        float gg = bi[600 + j] + bh[600 + j];
        float go = bi[900 + j] + bh[900 + j];
        const float* wi = W + j * 11;
        const float* wg = W + (600 + j) * 11;
        const float* wo = W + (900 + j) * 11;
#pragma unroll
        for (int i = 0; i < 11; i++) {
            gi = fmaf(wi[i], s[i], gi);
            gg = fmaf(wg[i], s[i], gg);
            go = fmaf(wo[i], s[i], go);
        }
        g_con[outb + j * Nq] = sigm(go) * tanh_(sigm(gi) * tanh_(gg));
    }
}

// ---------------- target cell ----------------
__global__ __launch_bounds__(128) void ht_kernel(const float* __restrict__ Wt,
                                                 const float* __restrict__ bti,
                                                 const float* __restrict__ bth) {
    int n = blockIdx.x * 128 + threadIdx.x;
    float e0 = g_eT[n], e1 = g_eT[Nq + n], e2 = g_eT[2 * Nq + n], e3 = g_eT[3 * Nq + n];
    for (int j = 0; j < 300; j++) {
        const float* w = Wt + j * 4;
        float gi = bti[j] + bth[j] + w[0] * e0 + w[1] * e1 + w[2] * e2 + w[3] * e3;
        w = Wt + (600 + j) * 4;
        float gg = bti[600 + j] + bth[600 + j] + w[0] * e0 + w[1] * e1 + w[2] * e2 + w[3] * e3;
        w = Wt + (900 + j) * 4;
        float go = bti[900 + j] + bth[900 + j] + w[0] * e0 + w[1] * e1 + w[2] * e2 + w[3] * e3;
        g_ht[j * Nq + n] = sigm(go) * tanh_(sigm(gi) * tanh_(gg));
    }
}

// ---------------- t=0: con1 = con directly (no wp, no relu) ----------------
__global__ void copy_t0() {
    int idx = blockIdx.x * 256 + threadIdx.x;
    if (idx < 3000 * 512) {
        int r = idx / 512, b = idx - r * 512;
        g_con1[r * Nq + b] = g_con[r * Nq + b];
    }
}

// q partials for t=0 columns (gemm0 never touches n<512)
__global__ __launch_bounds__(128) void q_t0_kernel() {
    int n = blockIdx.x * 128 + threadIdx.x;   // n < 512
    int k = blockIdx.y;
    const float* cp = g_con + k * 300 * Nq + n;
    float s = 0.f;
#pragma unroll 10
    for (int j = 0; j < 300; j++) s = fmaf(cp[j * Nq], g_u[j], s);
    g_qpart[k * Nq + n] = s;
    g_qpart[10 * Nq + k * Nq + n] = 0.f;
    g_qpart[20 * Nq + k * Nq + n] = 0.f;
}

// ---------------- tiled SGEMM with packed f32x2 FFMA ----------------
// MODE 0: con1 = relu(wpT . [con_t; con_{t-1}] + bp), M=300, n in [512,Nq)
//          epilogue also reduces q[z][k][n] = sum_o con1 * u[o]
// MODE 1: fc1 = relu(F1 . [con1; ht] + b1), M=200, all n   (fc1 NOT stored;
//          epilogue reduces wd[z][k][n] = sum_o relu(fc1) * F2[o])
template <int MODE>
__global__ __launch_bounds__(320) void gemm_kernel(const float* __restrict__ A,
                                                   const float* __restrict__ bias,
                                                   const float* __restrict__ F2p) {
    constexpr int BM = 100, BN = 256, BK = 16;
    constexpr int Mtot = (MODE == 0) ? 300 : 200;
    const int n0 = (MODE == 0 ? 512 : 0) + blockIdx.x * BN;
    const int k = blockIdx.y;
    const int o0 = blockIdx.z * BM;

    __shared__ __align__(16) unsigned char s_raw[BK * BM * 8 + BK * BN * 4]; // 12800+16384
    float2* As2 = (float2*)s_raw;                       // [BK][BM] pre-splatted (w,w)
    float* Bs = (float*)(s_raw + BK * BM * 8);          // [BK][BN]

    const int tid = threadIdx.x;
    const int tm = tid >> 4, tn = tid & 15;             // tm 0..19, tn 0..15
    const int nb = tn * 16;                             // 16 n per thread

    unsigned long long acc[5][8];
#pragma unroll
    for (int i = 0; i < 5; i++)
#pragma unroll
        for (int j = 0; j < 8; j++) acc[i][j] = 0ULL;

    const float* Ap = (MODE == 0) ? g_wpT : A;

    for (int h0 = 0; h0 < 600; h0 += BK) {
        // load A tile, splatted
#pragma unroll
        for (int it = 0; it < 5; it++) {
            int i = tid + it * 320;                     // i < 1600 always
            int kk = i / BM, m = i - kk * BM;
            int h = h0 + kk;
            float w = (h < 600) ? Ap[h * Mtot + o0 + m] : 0.f;
            As2[kk * BM + m] = make_float2(w, w);
        }
        // load B tile (float4)
        for (int i = tid; i < BK * BN / 4; i += 320) {
            int kk = i >> 6, c = (i & 63) * 4;
            int h = h0 + kk;
            float4 v;
            if (h >= 600) {
                v = make_float4(0.f, 0.f, 0.f, 0.f);
            } else if (MODE == 0) {
                v = (h < 300)
                        ? *(const float4*)&g_con[(k * 300 + h) * Nq + n0 + c]
                        : *(const float4*)&g_con[(k * 300 + h - 300) * Nq + (n0 - 512) + c];
            } else {
                v = (h < 300) ? *(const float4*)&g_con1[(k * 300 + h) * Nq + n0 + c]
                              : *(const float4*)&g_ht[(h - 300) * Nq + n0 + c];
            }
            *(float4*)&Bs[kk * BN + c] = v;
        }
        __syncthreads();
#pragma unroll
        for (int kk = 0; kk < BK; kk++) {
            unsigned long long a2[5], b2[8];
#pragma unroll
            for (int i = 0; i < 5; i++)
                a2[i] = ((const unsigned long long*)As2)[kk * BM + tm * 5 + i];
#pragma unroll
            for (int j4 = 0; j4 < 4; j4++) {
                ulonglong2 bv = *(const ulonglong2*)&Bs[kk * BN + nb + 4 * j4];
                b2[2 * j4] = bv.x;
                b2[2 * j4 + 1] = bv.y;
            }
#pragma unroll
            for (int i = 0; i < 5; i++)
#pragma unroll
                for (int j = 0; j < 8; j++) ffma2(acc[i][j], a2[i], b2[j]);
        }
        __syncthreads();
    }

    // epilogue: bias + relu, optional store, and linear reduction over o
    float pn[16];
#pragma unroll
    for (int c = 0; c < 16; c++) pn[c] = 0.f;
#pragma unroll
    for (int i = 0; i < 5; i++) {
        int o = o0 + tm * 5 + i;
        float bv = bias[o];
        float wU = (MODE == 0) ? g_u[o] : F2p[o];
        float r[16];
#pragma unroll
        for (int j = 0; j < 8; j++) {
            float2 v = *(float2*)&acc[i][j];
            r[2 * j] = fmaxf(v.x + bv, 0.f);
            r[2 * j + 1] = fmaxf(v.y + bv, 0.f);
        }
#pragma unroll
        for (int c = 0; c < 16; c++) pn[c] = fmaf(r[c], wU, pn[c]);
        if (MODE == 0) {
            float* dst = &g_con1[(k * 300 + o) * Nq + n0 + nb];
#pragma unroll
            for (int j4 = 0; j4 < 4; j4++)
                *(float4*)&dst[4 * j4] =
                    make_float4(r[4 * j4], r[4 * j4 + 1], r[4 * j4 + 2], r[4 * j4 + 3]);
        }
    }
    // cross-tm reduction of pn into per-z partial buffer
    __syncthreads();
    float* red = (float*)s_raw;   // [20][256]
#pragma unroll
    for (int c = 0; c < 16; c++) red[tm * 256 + nb + c] = pn[c];
    __syncthreads();
    if (tid < 256) {
        float s = 0.f;
#pragma unroll
        for (int r = 0; r < 20; r++) s += red[r * 256 + tid];
        float* dst = (MODE == 0) ? g_qpart : g_wdpart;
        dst[blockIdx.z * 10 * Nq + k * Nq + n0 + tid] = s;
    }
}

// ---------------- wdyn: finish fc2.F2, relu, faithful softmax scramble ----------------
__global__ __launch_bounds__(256) void wdyn_kernel(const float* __restrict__ F2,
                                                   const float* __restrict__ b2,
                                                   const float* __restrict__ AngleM) {
    int n = blockIdx.x * 256 + threadIdx.x;
    int t = n >> 9, b = n & 511;
    float wd[10], mx = -1e30f;
#pragma unroll
    for (int k = 0; k < 10; k++) {
        float acc = b2[0] + g_wdpart[k * Nq + n] + g_wdpart[10 * Nq + k * Nq + n];
        float fl8 = g_xT[(80 + k) * Nq + n];
        float angv = fabsf(g_xT[(100 + k) * Nq + n] - AngleM[k]) * (1.0f / 360.0f);
        acc = fmaf(fl8, F2[200], fmaf(angv, F2[201], acc));
        wd[k] = fmaxf(acc, 0.f);
        mx = fmaxf(mx, wd[k]);
    }
    float e[10], den = 0.f;
#pragma unroll
    for (int k = 0; k < 10; k++) { e[k] = __expf(wd[k] - mx); den += e[k]; }
    float inv = __fdividef(1.f, den);
#pragma unroll
    for (int k = 0; k < 10; k++) g_sm[t * 5120 + k * 512 + b] = e[k] * inv;
}

// ---------------- final: collapsed linear tail ----------------
__global__ __launch_bounds__(256) void final_kernel(const float* __restrict__ labels,
                                                    const float* __restrict__ a,
                                                    const float* __restrict__ biasout,
                                                    float* __restrict__ out) {
    int n = blockIdx.x * 256 + threadIdx.x;
    int t = n >> 9, b = n & 511;
    float catU = 0.f;
#pragma unroll
    for (int k = 0; k < 10; k++) {
        float q = g_qpart[k * Nq + n] + g_qpart[10 * Nq + k * Nq + n] +
                  g_qpart[20 * Nq + k * Nq + n];
        catU = fmaf(q, g_sm[t * 5120 + b * 10 + k], catU);  // faithful flat reshape
    }
    float disU = 0.f;
#pragma unroll
    for (int f = 0; f < 17; f++) {
        float s = 0.f;
#pragma unroll
        for (int k = 0; k < 10; k++) s = fmaf(g_xT[((11 + f) * 10 + k) * Nq + n], g_wA[k], s);
        disU = fmaf(s, g_v[f], disU);
    }
    float aa = a[0];
    float pred = aa * (catU + g_c[0]) + (1.f - aa) * (disU + g_c[1]) + biasout[0];
    out[n] = pred;                    // preds [T,B,1], n = t*B+b
    out[Nq + n] = labels[b * Tq + t]; // labels_r [T,B,1]
}

// ---------------- launch ----------------
extern "C" void kernel_launch(void* const* d_in, const int* in_sizes, int n_in,
                              void* d_out, int out_size) {
    const float* li      = (const float*)d_in[0];
    const float* labels  = (const float*)d_in[1];
    const float* extras  = (const float*)d_in[2];
    const float* DisM    = (const float*)d_in[3];
    const float* AngleM  = (const float*)d_in[4];
    const float* Wih     = (const float*)d_in[5];
    const float* b_ih    = (const float*)d_in[6];
    const float* b_hh    = (const float*)d_in[7];
    const float* Wt      = (const float*)d_in[8];
    const float* bt_ih   = (const float*)d_in[9];
    const float* bt_hh   = (const float*)d_in[10];
    const float* wp      = (const float*)d_in[11];
    const float* bp      = (const float*)d_in[12];
    const float* F1      = (const float*)d_in[13];
    const float* b1      = (const float*)d_in[14];
    const float* F2      = (const float*)d_in[15];
    const float* b2      = (const float*)d_in[16];
    const float* biasout = (const float*)d_in[22];
    const float* a       = (const float*)d_in[23];
    const float* ff      = (const float*)d_in[17];
    const float* bff     = (const float*)d_in[18];
    const float* fuse1   = (const float*)d_in[19];
    const float* biasf   = (const float*)d_in[20];
    const float* Wout    = (const float*)d_in[21];
    float* out = (float*)d_out;

    prep_small<<<1, 320>>>(DisM, fuse1, ff, biasf, bff, Wout);
    prep_wpT<<<(600 * 300 + 255) / 256, 256>>>(wp);
    transpose_kernel<<<284 * Nq / 256, 256>>>(li, extras);
    cells_kernel<<<dim3(Nq / 128, 10), 128>>>(Wih, b_ih, b_hh);
    ht_kernel<<<Nq / 128, 128>>>(Wt, bt_ih, bt_hh);
    copy_t0<<<3000 * 512 / 256, 256>>>();
    q_t0_kernel<<<dim3(4, 10), 128>>>();
    gemm_kernel<0><<<dim3((Nq - 512) / 256, 10, 3), 320>>>(nullptr, bp, nullptr);
    gemm_kernel<1><<<dim3(Nq / 256, 10, 2), 320>>>(F1, b1, F2);
    wdyn_kernel<<<Nq / 256, 256>>>(F2, b2, AngleM);
    final_kernel<<<Nq / 256, 256>>>(labels, a, biasout, out);
}

// round 6
// speedup vs baseline: 1.2182x; 1.2182x over previous
#include <cuda_runtime.h>

#define Bq 512
#define Tq 32
#define Nq 16384   // Tq*Bq, power of two: n = t*512 + b

// ---------------- scratch (static device arrays; no runtime alloc) ----------------
__device__ __align__(16) float g_xT[280 * Nq];    // [i*10+k][n] transposed local_inputs
__device__ __align__(16) float g_eT[4 * Nq];      // [i][n] transposed extras
__device__ __align__(16) float g_con[3000 * Nq];  // [k*300+j][n]
__device__ __align__(16) float g_con1[3000 * Nq]; // [k*300+j][n]
__device__ __align__(16) float g_ht[300 * Nq];    // [j][n]
__device__ __align__(16) float g_sm[Tq * 10 * Bq];// [t][r][c] softmaxed wdyn
__device__ __align__(16) float g_q[10 * Nq];      // con1 . u   (full, fused in gemm0)
__device__ __align__(16) float g_wd[10 * Nq];     // relu(fc1) . F2 (full, fused in gemm1)
__device__ __align__(16) float g_u[300];          // fuse1 @ Wout
__device__ __align__(16) float g_v[17];           // ff^T @ Wout
__device__ __align__(16) float g_wA[10];          // softmax(DisM)
__device__ __align__(16) float g_c[2];            // biasf.Wout, bff.Wout
__device__ __align__(16) float g_wpT[600 * 300];  // wp transposed to [h][o]

// ---------------- helpers ----------------
__device__ __forceinline__ float sigm(float x) {
    float e = __expf(-x);
    return __fdividef(1.f, 1.f + e);
}
__device__ __forceinline__ float tanh_(float x) {
    float e = __expf(-2.f * fabsf(x));
    float t = __fdividef(1.f - e, 1.f + e);
    return copysignf(t, x);
}

// ---------------- prep: tiny precomputations ----------------
__global__ void prep_small(const float* __restrict__ DisM, const float* __restrict__ fuse1,
                           const float* __restrict__ ff, const float* __restrict__ biasf,
                           const float* __restrict__ bff, const float* __restrict__ Wout) {
    int tid = threadIdx.x;
    if (tid < 300) {
        float s = 0.f;
        for (int o = 0; o < 100; o++) s = fmaf(fuse1[tid * 100 + o], Wout[o], s);
        g_u[tid] = s;
    }
    if (tid < 17) {
        float s = 0.f;
        for (int o = 0; o < 100; o++) s = fmaf(ff[o * 17 + tid], Wout[o], s);
        g_v[tid] = s;
    }
    if (tid == 300) {
        float s = 0.f;
        for (int o = 0; o < 100; o++) s = fmaf(biasf[o], Wout[o], s);
        g_c[0] = s;
    }
    if (tid == 301) {
        float s = 0.f;
        for (int o = 0; o < 100; o++) s = fmaf(bff[o], Wout[o], s);
        g_c[1] = s;
    }
    if (tid == 302) {
        float m = DisM[0];
        for (int k = 1; k < 10; k++) m = fmaxf(m, DisM[k]);
        float e[10], d = 0.f;
        for (int k = 0; k < 10; k++) { e[k] = __expf(DisM[k] - m); d += e[k]; }
        for (int k = 0; k < 10; k++) g_wA[k] = e[k] / d;
    }
}

__global__ void prep_wpT(const float* __restrict__ wp) {
    int idx = blockIdx.x * 256 + threadIdx.x;
    if (idx < 600 * 300) {
        int h = idx / 300, o = idx - h * 300;
        g_wpT[idx] = wp[o * 600 + h];
    }
}

// ---------------- transpose inputs to [feature][n] layout ----------------
__global__ void transpose_kernel(const float* __restrict__ li, const float* __restrict__ ex) {
    int idx = blockIdx.x * 256 + threadIdx.x;
    const int total1 = 280 * Nq;
    if (idx < total1) {
        int row = idx >> 14, n = idx & (Nq - 1);
        int i = row / 10, kk = row - i * 10;
        int t = n >> 9, b = n & 511;
        g_xT[idx] = li[((b * Tq + t) * 28 + i) * 10 + kk];
    } else {
        int j = idx - total1;
        if (j < 4 * Nq) {
            int i = j >> 14, n = j & (Nq - 1);
            int t = n >> 9, b = n & 511;
            g_eT[j] = ex[(b * Tq + t) * 4 + i];
        }
    }
}

// ---------------- cells: per-neighbor zero-state LSTM cell (f gate unused) ----------------
__global__ __launch_bounds__(128) void cells_kernel(const float* __restrict__ Wih,
                                                    const float* __restrict__ b_ih,
                                                    const float* __restrict__ b_hh) {
    int n = blockIdx.x * 128 + threadIdx.x;
    int k = blockIdx.y;
    float s[11];
#pragma unroll
    for (int i = 0; i < 11; i++) s[i] = g_xT[(i * 10 + k) * Nq + n];
    const float* W = Wih + k * 13200;   // [1200][11]
    const float* bi = b_ih + k * 1200;
    const float* bh = b_hh + k * 1200;
    int outb = k * 300 * Nq + n;
    for (int j = 0; j < 300; j++) {
        float gi = bi[j] + bh[j];
        float gg = bi[600 + j] + bh[600 + j];
        float go = bi[900 + j] + bh[900 + j];
        const float* wi = W + j * 11;
        const float* wg = W + (600 + j) * 11;
        const float* wo = W + (900 + j) * 11;
#pragma unroll
        for (int i = 0; i < 11; i++) {
            gi = fmaf(wi[i], s[i], gi);
            gg = fmaf(wg[i], s[i], gg);
            go = fmaf(wo[i], s[i], go);
        }
        g_con[outb + j * Nq] = sigm(go) * tanh_(sigm(gi) * tanh_(gg));
    }
}

// ---------------- target cell ----------------
__global__ __launch_bounds__(128) void ht_kernel(const float* __restrict__ Wt,
                                                 const float* __restrict__ bti,
                                                 const float* __restrict__ bth) {
    int n = blockIdx.x * 128 + threadIdx.x;
    float e0 = g_eT[n], e1 = g_eT[Nq + n], e2 = g_eT[2 * Nq + n], e3 = g_eT[3 * Nq + n];
    for (int j = 0; j < 300; j++) {
        const float* w = Wt + j * 4;
        float gi = bti[j] + bth[j] + w[0] * e0 + w[1] * e1 + w[2] * e2 + w[3] * e3;
        w = Wt + (600 + j) * 4;
        float gg = bti[600 + j] + bth[600 + j] + w[0] * e0 + w[1] * e1 + w[2] * e2 + w[3] * e3;
        w = Wt + (900 + j) * 4;
        float go = bti[900 + j] + bth[900 + j] + w[0] * e0 + w[1] * e1 + w[2] * e2 + w[3] * e3;
        g_ht[j * Nq + n] = sigm(go) * tanh_(sigm(gi) * tanh_(gg));
    }
}

// ---------------- t=0: con1 = con directly (no wp, no relu) ----------------
__global__ void copy_t0() {
    int idx = blockIdx.x * 256 + threadIdx.x;
    if (idx < 3000 * 512) {
        int r = idx / 512, b = idx - r * 512;
        g_con1[r * Nq + b] = g_con[r * Nq + b];
    }
}

// q for t=0 columns (gemm0 never touches n<512)
__global__ __launch_bounds__(128) void q_t0_kernel() {
    int n = blockIdx.x * 128 + threadIdx.x;   // n < 512
    int k = blockIdx.y;
    const float* cp = g_con + k * 300 * Nq + n;
    float s = 0.f;
#pragma unroll 10
    for (int j = 0; j < 300; j++) s = fmaf(cp[j * Nq], g_u[j], s);
    g_q[k * Nq + n] = s;
}

// ---------------- full-M SGEMM, fused epilogue reduction ----------------
// MODE 0: con1 = relu(wpT . [con_t; con_{t-1}] + bp), M=300, n in [512,Nq)
//          also q[k][n] = sum_o con1[o][n]*u[o]      (stores con1 AND q)
// MODE 1: fc1 = relu(F1 . [con1; ht] + b1), M=200, all n (fc1 never stored;
//          wd[k][n] = sum_o relu(fc1[o][n])*F2[o])
// 320 threads as 20(tm) x 16(tn); micro-tile RM x 8; BK=20 (600/20=30 tiles).
template <int MODE>
__global__ __launch_bounds__(320, 1) void gemm_kernel(const float* __restrict__ A,
                                                      const float* __restrict__ bias,
                                                      const float* __restrict__ F2p) {
    constexpr int Mtot = (MODE == 0) ? 300 : 200;
    constexpr int RM = Mtot / 20;             // 15 or 10
    constexpr int BK = 20;
    constexpr int BN = 128;
    constexpr int AQ = BK * Mtot / 4;         // float4 per A tile: 1500 / 1000
    constexpr int NA = (AQ + 319) / 320;      // 5 / 4

    __shared__ float As[BK * Mtot];           // 24 KB / 16 KB
    __shared__ float Bs[BK * BN];             // 10.25 KB

    const int tid = threadIdx.x;
    const int tm = tid >> 4, tn = tid & 15;
    const int n0 = (MODE == 0 ? 512 : 0) + blockIdx.x * BN;
    const int k = blockIdx.y;
    const float* Ap = (MODE == 0) ? (const float*)g_wpT : A;

    float acc[RM][8];
#pragma unroll
    for (int i = 0; i < RM; i++)
#pragma unroll
        for (int j = 0; j < 8; j++) acc[i][j] = 0.f;

    float4 abuf[NA];
    float4 bbuf[2];

    // prefetch tile 0
    {
        const float4* src = (const float4*)(Ap);
#pragma unroll
        for (int it = 0; it < NA; it++) {
            int idx = tid + it * 320;
            if (idx < AQ) abuf[it] = src[idx];
        }
#pragma unroll
        for (int it = 0; it < 2; it++) {
            int i = tid + it * 320;           // < 640
            int kk = i >> 5, c = (i & 31) * 4;
            int h = kk;                       // tile 0
            if (MODE == 0) {
                bbuf[it] = *(const float4*)&g_con[(k * 300 + h) * Nq + n0 + c];
            } else {
                bbuf[it] = *(const float4*)&g_con1[(k * 300 + h) * Nq + n0 + c];
            }
        }
    }

    for (int t = 0; t < 30; t++) {
        // store prefetched tile to smem
#pragma unroll
        for (int it = 0; it < NA; it++) {
            int idx = tid + it * 320;
            if (idx < AQ) ((float4*)As)[idx] = abuf[it];
        }
#pragma unroll
        for (int it = 0; it < 2; it++) {
            int i = tid + it * 320;
            ((float4*)Bs)[i] = bbuf[it];
        }
        __syncthreads();

        // prefetch next tile while computing
        if (t < 29) {
            const float4* src = (const float4*)(Ap + (t + 1) * BK * Mtot);
#pragma unroll
            for (int it = 0; it < NA; it++) {
                int idx = tid + it * 320;
                if (idx < AQ) abuf[it] = src[idx];
            }
#pragma unroll
            for (int it = 0; it < 2; it++) {
                int i = tid + it * 320;
                int kk = i >> 5, c = (i & 31) * 4;
                int h = (t + 1) * BK + kk;
                if (MODE == 0) {
                    bbuf[it] = (h < 300)
                        ? *(const float4*)&g_con[(k * 300 + h) * Nq + n0 + c]
                        : *(const float4*)&g_con[(k * 300 + h - 300) * Nq + (n0 - 512) + c];
                } else {
                    bbuf[it] = (h < 300)
                        ? *(const float4*)&g_con1[(k * 300 + h) * Nq + n0 + c]
                        : *(const float4*)&g_ht[(h - 300) * Nq + n0 + c];
                }
            }
        }

        // compute
#pragma unroll 5
        for (int kk = 0; kk < BK; kk++) {
            float a[RM];
#pragma unroll
            for (int i = 0; i < RM; i++) a[i] = As[kk * Mtot + tm * RM + i];
            float4 b0 = *(const float4*)&Bs[kk * BN + tn * 8];
            float4 b1 = *(const float4*)&Bs[kk * BN + tn * 8 + 4];
            float b[8] = {b0.x, b0.y, b0.z, b0.w, b1.x, b1.y, b1.z, b1.w};
#pragma unroll
            for (int i = 0; i < RM; i++)
#pragma unroll
                for (int j = 0; j < 8; j++) acc[i][j] = fmaf(a[i], b[j], acc[i][j]);
        }
        __syncthreads();
    }

    // epilogue: bias + relu (+ store con1 in MODE 0), reduce over o with u / F2
    float pn[8];
#pragma unroll
    for (int j = 0; j < 8; j++) pn[j] = 0.f;
#pragma unroll
    for (int i = 0; i < RM; i++) {
        int o = tm * RM + i;
        float bv = bias[o];
        float wU = (MODE == 0) ? g_u[o] : F2p[o];
        float r[8];
#pragma unroll
        for (int j = 0; j < 8; j++) r[j] = fmaxf(acc[i][j] + bv, 0.f);
#pragma unroll
        for (int j = 0; j < 8; j++) pn[j] = fmaf(r[j], wU, pn[j]);
        if (MODE == 0) {
            float* dst = &g_con1[(k * 300 + o) * Nq + n0 + tn * 8];
            *(float4*)&dst[0] = make_float4(r[0], r[1], r[2], r[3]);
            *(float4*)&dst[4] = make_float4(r[4], r[5], r[6], r[7]);
        }
    }
    // cross-tm reduction (reuse As as scratch: 20*128 floats)
    float* red = As;
#pragma unroll
    for (int j = 0; j < 8; j++) red[tm * BN + tn * 8 + j] = pn[j];
    __syncthreads();
    if (tid < BN) {
        float s = 0.f;
#pragma unroll
        for (int r = 0; r < 20; r++) s += red[r * BN + tid];
        float* dst = (MODE == 0) ? g_q : g_wd;
        dst[k * Nq + n0 + tid] = s;
    }
}

// ---------------- wdyn: finish fc2.F2, relu, faithful softmax scramble ----------------
__global__ __launch_bounds__(256) void wdyn_kernel(const float* __restrict__ F2,
                                                   const float* __restrict__ b2,
                                                   const float* __restrict__ AngleM) {
    int n = blockIdx.x * 256 + threadIdx.x;
    int t = n >> 9, b = n & 511;
    float wd[10], mx = -1e30f;
#pragma unroll
    for (int k = 0; k < 10; k++) {
        float acc = b2[0] + g_wd[k * Nq + n];
        float fl8 = g_xT[(80 + k) * Nq + n];
        float angv = fabsf(g_xT[(100 + k) * Nq + n] - AngleM[k]) * (1.0f / 360.0f);
        acc = fmaf(fl8, F2[200], fmaf(angv, F2[201], acc));
        wd[k] = fmaxf(acc, 0.f);
        mx = fmaxf(mx, wd[k]);
    }
    float e[10], den = 0.f;
#pragma unroll
    for (int k = 0; k < 10; k++) { e[k] = __expf(wd[k] - mx); den += e[k]; }
    float inv = __fdividef(1.f, den);
#pragma unroll
    for (int k = 0; k < 10; k++) g_sm[t * 5120 + k * 512 + b] = e[k] * inv;
}

// ---------------- final: collapsed linear tail ----------------
__global__ __launch_bounds__(256) void final_kernel(const float* __restrict__ labels,
                                                    const float* __restrict__ a,
                                                    const float* __restrict__ biasout,
                                                    float* __restrict__ out) {
    int n = blockIdx.x * 256 + threadIdx.x;
    int t = n >> 9, b = n & 511;
    float catU = 0.f;
#pragma unroll
    for (int k = 0; k < 10; k++) {
        float q = g_q[k * Nq + n];
        catU = fmaf(q, g_sm[t * 5120 + b * 10 + k], catU);  // faithful flat reshape
    }
    float disU = 0.f;
#pragma unroll
    for (int f = 0; f < 17; f++) {
        float s = 0.f;
#pragma unroll
        for (int k = 0; k < 10; k++) s = fmaf(g_xT[((11 + f) * 10 + k) * Nq + n], g_wA[k], s);
        disU = fmaf(s, g_v[f], disU);
    }
    float aa = a[0];
    float pred = aa * (catU + g_c[0]) + (1.f - aa) * (disU + g_c[1]) + biasout[0];
    out[n] = pred;                    // preds [T,B,1], n = t*B+b
    out[Nq + n] = labels[b * Tq + t]; // labels_r [T,B,1]
}

// ---------------- launch ----------------
extern "C" void kernel_launch(void* const* d_in, const int* in_sizes, int n_in,
                              void* d_out, int out_size) {
    const float* li      = (const float*)d_in[0];
    const float* labels  = (const float*)d_in[1];
    const float* extras  = (const float*)d_in[2];
    const float* DisM    = (const float*)d_in[3];
    const float* AngleM  = (const float*)d_in[4];
    const float* Wih     = (const float*)d_in[5];
    const float* b_ih    = (const float*)d_in[6];
    const float* b_hh    = (const float*)d_in[7];
    const float* Wt      = (const float*)d_in[8];
    const float* bt_ih   = (const float*)d_in[9];
    const float* bt_hh   = (const float*)d_in[10];
    const float* wp      = (const float*)d_in[11];
    const float* bp      = (const float*)d_in[12];
    const float* F1      = (const float*)d_in[13];
    const float* b1      = (const float*)d_in[14];
    const float* F2      = (const float*)d_in[15];
    const float* b2      = (const float*)d_in[16];
    const float* ff      = (const float*)d_in[17];
    const float* bff     = (const float*)d_in[18];
    const float* fuse1   = (const float*)d_in[19];
    const float* biasf   = (const float*)d_in[20];
    const float* Wout    = (const float*)d_in[21];
    const float* biasout = (const float*)d_in[22];
    const float* a       = (const float*)d_in[23];
    float* out = (float*)d_out;

    prep_small<<<1, 320>>>(DisM, fuse1, ff, biasf, bff, Wout);
    prep_wpT<<<(600 * 300 + 255) / 256, 256>>>(wp);
    transpose_kernel<<<284 * Nq / 256, 256>>>(li, extras);
    cells_kernel<<<dim3(Nq / 128, 10), 128>>>(Wih, b_ih, b_hh);
    ht_kernel<<<Nq / 128, 128>>>(Wt, bt_ih, bt_hh);
    copy_t0<<<3000 * 512 / 256, 256>>>();
    q_t0_kernel<<<dim3(4, 10), 128>>>();
    gemm_kernel<0><<<dim3((Nq - 512) / 128, 10), 320>>>(nullptr, bp, nullptr);
    gemm_kernel<1><<<dim3(Nq / 128, 10), 320>>>(F1, b1, F2);
    wdyn_kernel<<<Nq / 256, 256>>>(F2, b2, AngleM);
    final_kernel<<<Nq / 256, 256>>>(labels, a, biasout, out);
}

// round 11
// speedup vs baseline: 6.1472x; 5.0463x over previous
#include <cuda_runtime.h>
#include <cuda_fp16.h>
#include <cstdint>

#define Bq 512
#define Tq 32
#define Nq 16384   // Tq*Bq, power of two: n = t*512 + b

// ---------------- scratch (static device arrays; no runtime alloc) ----------------
__device__ __align__(16) float  g_xT[280 * Nq];    // [i*10+k][n] transposed local_inputs
__device__ __align__(16) float  g_eT[4 * Nq];      // [i][n] transposed extras
__device__ __align__(16) float  g_con[3000 * Nq];  // fp32 con (q_t0 / copy_t0 source)
__device__ __align__(16) __half g_conh[3000 * Nq]; // fp16 con (gemm0 B operand)
__device__ __align__(16) __half g_con1h[3000 * Nq];// fp16 con1 (gemm1 B operand)
__device__ __align__(16) __half g_hth[300 * Nq];   // fp16 ht   (gemm1 B operand)
__device__ __align__(16) float  g_sm[Tq * 10 * Bq];// [t][r][c] softmaxed wdyn
__device__ __align__(16) float  g_qp[3 * 10 * Nq]; // per-z partials of con1 . u
__device__ __align__(16) float  g_wdp[2 * 10 * Nq];// per-z partials of relu(fc1) . F2
__device__ __align__(16) float  g_u[300];          // fuse1 @ Wout
__device__ __align__(16) float  g_v[17];           // ff^T @ Wout
__device__ __align__(16) float  g_wA[10];          // softmax(DisM)
__device__ __align__(16) float  g_c[2];            // biasf.Wout, bff.Wout
// zero-padded fp16 weight images: [o][h] row-major, K padded to 640, M padded to 384/256
__device__ __align__(16) __half g_W0h[384 * 640];  // wp   (300x600 live)
__device__ __align__(16) __half g_W1h[256 * 640];  // F1^T (200x600 live)

// ---------------- mma helpers (generic PTX, assembles for plain sm_103) ----------
__device__ __forceinline__ uint32_t smem_u32(const void* p) {
    uint32_t a;
    asm("{ .reg .u64 t; cvta.to.shared.u64 t, %1; cvt.u32.u64 %0, t; }" : "=r"(a) : "l"(p));
    return a;
}
#define LDSM4(r0, r1, r2, r3, addr)                                              \
    asm volatile("ldmatrix.sync.aligned.m8n8.x4.shared.b16 {%0,%1,%2,%3}, [%4];" \
                 : "=r"(r0), "=r"(r1), "=r"(r2), "=r"(r3) : "r"(addr))
#define LDSM4T(r0, r1, r2, r3, addr)                                                   \
    asm volatile("ldmatrix.sync.aligned.m8n8.x4.trans.shared.b16 {%0,%1,%2,%3}, [%4];" \
                 : "=r"(r0), "=r"(r1), "=r"(r2), "=r"(r3) : "r"(addr))
#define MMA16816(c, a, b0, b1)                                                   \
    asm volatile("mma.sync.aligned.m16n8k16.row.col.f32.f16.f16.f32 "            \
                 "{%0,%1,%2,%3}, {%4,%5,%6,%7}, {%8,%9}, {%0,%1,%2,%3};"         \
                 : "+f"((c)[0]), "+f"((c)[1]), "+f"((c)[2]), "+f"((c)[3])        \
                 : "r"((a)[0]), "r"((a)[1]), "r"((a)[2]), "r"((a)[3]),           \
                   "r"(b0), "r"(b1))

// ---------------- math helpers ----------------
__device__ __forceinline__ float sigm(float x) {
    float e = __expf(-x);
    return __fdividef(1.f, 1.f + e);
}
__device__ __forceinline__ float tanh_(float x) {
    float e = __expf(-2.f * fabsf(x));
    float t = __fdividef(1.f - e, 1.f + e);
    return copysignf(t, x);
}

// ---------------- prep: tiny precomputations ----------------
__global__ void prep_small(const float* __restrict__ DisM, const float* __restrict__ fuse1,
                           const float* __restrict__ ff, const float* __restrict__ biasf,
                           const float* __restrict__ bff, const float* __restrict__ Wout) {
    int tid = threadIdx.x;
    if (tid < 300) {
        float s = 0.f;
        for (int o = 0; o < 100; o++) s = fmaf(fuse1[tid * 100 + o], Wout[o], s);
        g_u[tid] = s;
    }
    if (tid < 17) {
        float s = 0.f;
        for (int o = 0; o < 100; o++) s = fmaf(ff[o * 17 + tid], Wout[o], s);
        g_v[tid] = s;
    }
    if (tid == 300) {
        float s = 0.f;
        for (int o = 0; o < 100; o++) s = fmaf(biasf[o], Wout[o], s);
        g_c[0] = s;
    }
    if (tid == 301) {
        float s = 0.f;
        for (int o = 0; o < 100; o++) s = fmaf(bff[o], Wout[o], s);
        g_c[1] = s;
    }
    if (tid == 302) {
        float m = DisM[0];
        for (int k = 1; k < 10; k++) m = fmaxf(m, DisM[k]);
        float e[10], d = 0.f;
        for (int k = 0; k < 10; k++) { e[k] = __expf(DisM[k] - m); d += e[k]; }
        for (int k = 0; k < 10; k++) g_wA[k] = e[k] / d;
    }
}

// zero-padded fp16 weight images
__global__ void prep_Wh(const float* __restrict__ wp, const float* __restrict__ F1) {
    int idx = blockIdx.x * 256 + threadIdx.x;
    const int t0 = 384 * 640;
    if (idx < t0) {
        int o = idx / 640, h = idx - o * 640;
        g_W0h[idx] = __float2half_rn((o < 300 && h < 600) ? wp[o * 600 + h] : 0.f);
    } else {
        int j = idx - t0;
        if (j < 256 * 640) {
            int o = j / 640, h = j - o * 640;
            g_W1h[j] = __float2half_rn((o < 200 && h < 600) ? F1[h * 200 + o] : 0.f);
        }
    }
}

// ---------------- transpose inputs to [feature][n] layout ----------------
__global__ void transpose_kernel(const float* __restrict__ li, const float* __restrict__ ex) {
    int idx = blockIdx.x * 256 + threadIdx.x;
    const int total1 = 280 * Nq;
    if (idx < total1) {
        int row = idx >> 14, n = idx & (Nq - 1);
        int i = row / 10, kk = row - i * 10;
        int t = n >> 9, b = n & 511;
        g_xT[idx] = li[((b * Tq + t) * 28 + i) * 10 + kk];
    } else {
        int j = idx - total1;
        if (j < 4 * Nq) {
            int i = j >> 14, n = j & (Nq - 1);
            int t = n >> 9, b = n & 511;
            g_eT[j] = ex[(b * Tq + t) * 4 + i];
        }
    }
}

// ---------------- cells: per-neighbor zero-state LSTM cell (f gate unused) ----------------
__global__ __launch_bounds__(128) void cells_kernel(const float* __restrict__ Wih,
                                                    const float* __restrict__ b_ih,
                                                    const float* __restrict__ b_hh) {
    int n = blockIdx.x * 128 + threadIdx.x;
    int k = blockIdx.y;
    float s[11];
#pragma unroll
    for (int i = 0; i < 11; i++) s[i] = g_xT[(i * 10 + k) * Nq + n];
    const float* W = Wih + k * 13200;   // [1200][11]
    const float* bi = b_ih + k * 1200;
    const float* bh = b_hh + k * 1200;
    int outb = k * 300 * Nq + n;
    for (int j = 0; j < 300; j++) {
        float gi = bi[j] + bh[j];
        float gg = bi[600 + j] + bh[600 + j];
        float go = bi[900 + j] + bh[900 + j];
        const float* wi = W + j * 11;
        const float* wg = W + (600 + j) * 11;
        const float* wo = W + (900 + j) * 11;
#pragma unroll
        for (int i = 0; i < 11; i++) {
            gi = fmaf(wi[i], s[i], gi);
            gg = fmaf(wg[i], s[i], gg);
            go = fmaf(wo[i], s[i], go);
        }
        float val = sigm(go) * tanh_(sigm(gi) * tanh_(gg));
        g_con[outb + j * Nq] = val;
        g_conh[outb + j * Nq] = __float2half_rn(val);
    }
}

// ---------------- target cell (fp16 output for gemm1) ----------------
__global__ __launch_bounds__(128) void ht_kernel(const float* __restrict__ Wt,
                                                 const float* __restrict__ bti,
                                                 const float* __restrict__ bth) {
    int n = blockIdx.x * 128 + threadIdx.x;
    float e0 = g_eT[n], e1 = g_eT[Nq + n], e2 = g_eT[2 * Nq + n], e3 = g_eT[3 * Nq + n];
    for (int j = 0; j < 300; j++) {
        const float* w = Wt + j * 4;
        float gi = bti[j] + bth[j] + w[0] * e0 + w[1] * e1 + w[2] * e2 + w[3] * e3;
        w = Wt + (600 + j) * 4;
        float gg = bti[600 + j] + bth[600 + j] + w[0] * e0 + w[1] * e1 + w[2] * e2 + w[3] * e3;
        w = Wt + (900 + j) * 4;
        float go = bti[900 + j] + bth[900 + j] + w[0] * e0 + w[1] * e1 + w[2] * e2 + w[3] * e3;
        g_hth[j * Nq + n] = __float2half_rn(sigm(go) * tanh_(sigm(gi) * tanh_(gg)));
    }
}

// ---------------- t=0: con1 = con (fp16 image) ----------------
__global__ void copy_t0() {
    int idx = blockIdx.x * 256 + threadIdx.x;
    if (idx < 3000 * 512) {
        int r = idx / 512, b = idx - r * 512;
        g_con1h[r * Nq + b] = __float2half_rn(g_con[r * Nq + b]);
    }
}

// q partials for t=0 columns (gemm0 never touches n<512)
__global__ __launch_bounds__(128) void q_t0_kernel() {
    int n = blockIdx.x * 128 + threadIdx.x;   // n < 512
    int k = blockIdx.y;
    const float* cp = g_con + k * 300 * Nq + n;
    float s = 0.f;
#pragma unroll 10
    for (int j = 0; j < 300; j++) s = fmaf(cp[j * Nq], g_u[j], s);
    g_qp[k * Nq + n] = s;
    g_qp[(10 + k) * Nq + n] = 0.f;
    g_qp[(20 + k) * Nq + n] = 0.f;
}

// ---------------- tensor-core GEMM (mma.sync m16n8k16 fp16 -> fp32) ----------------
// D[o][n] = sum_h W[o][h] * X[h][n];  CTA tile 128(o) x 128(n), BK=32, K pad 640.
// MODE 0: X = [conh_t ; conh_{t-1}], out con1h = relu(D + bp); partial q = sum_o con1*u
// MODE 1: X = [con1h ; hth], nothing stored but partial wd = sum_o relu(D + b1)*F2
template <int MODE>
__global__ __launch_bounds__(256) void mma_gemm(const float* __restrict__ bias,
                                                const float* __restrict__ F2p) {
    constexpr int Mtot = (MODE == 0) ? 300 : 200;
    __shared__ __align__(16) __half sA[128 * 40];   // [o][k], stride 40
    __shared__ __align__(16) __half sB[32 * 136];   // [k][n], stride 136

    const int tid = threadIdx.x;
    const int lane = tid & 31, wid = tid >> 5;
    const int wm = wid >> 1, wn = wid & 1;          // 4 x 2 warp grid
    const int n0b = (MODE == 0 ? 512 : 0) + blockIdx.x * 128;
    const int k3 = blockIdx.y * 300;
    const int bm0 = blockIdx.z * 128;
    const __half* Wimg = (MODE == 0) ? g_W0h : g_W1h;

    float c[2][8][4];
#pragma unroll
    for (int mi = 0; mi < 2; mi++)
#pragma unroll
        for (int nt = 0; nt < 8; nt++)
#pragma unroll
            for (int e = 0; e < 4; e++) c[mi][nt][e] = 0.f;

    const int arow = tid >> 1, acol = (tid & 1) * 16;   // A: 2 thr/row, 16 halves each
    const int brow = tid >> 3, bcol = (tid & 7) * 16;   // B: 8 thr/row, 16 halves each

    for (int it = 0; it < 20; it++) {
        const int h0 = it * 32;
        // global -> regs
        uint4 av0 = *(const uint4*)&Wimg[(bm0 + arow) * 640 + h0 + acol];
        uint4 av1 = *(const uint4*)&Wimg[(bm0 + arow) * 640 + h0 + acol + 8];
        uint4 bv0, bv1;
        {
            int h = h0 + brow;
            if (h < 600) {
                const __half* p;
                if (MODE == 0)
                    p = (h < 300) ? &g_conh[(k3 + h) * Nq + n0b + bcol]
                                  : &g_conh[(k3 + h - 300) * Nq + (n0b - 512) + bcol];
                else
                    p = (h < 300) ? &g_con1h[(k3 + h) * Nq + n0b + bcol]
                                  : &g_hth[(h - 300) * Nq + n0b + bcol];
                bv0 = ((const uint4*)p)[0];
                bv1 = ((const uint4*)p)[1];
            } else {
                bv0 = make_uint4(0, 0, 0, 0);
                bv1 = bv0;
            }
        }
        __syncthreads();
        *(uint4*)&sA[arow * 40 + acol] = av0;
        *(uint4*)&sA[arow * 40 + acol + 8] = av1;
        *(uint4*)&sB[brow * 136 + bcol] = bv0;
        *(uint4*)&sB[brow * 136 + bcol + 8] = bv1;
        __syncthreads();

#pragma unroll
        for (int kk = 0; kk < 2; kk++) {
            uint32_t a[2][4];
#pragma unroll
            for (int mi = 0; mi < 2; mi++) {
                int row = wm * 32 + mi * 16 + (lane & 15);
                int col = kk * 16 + ((lane >> 4) << 3);
                uint32_t ad = smem_u32(&sA[row * 40 + col]);
                LDSM4(a[mi][0], a[mi][1], a[mi][2], a[mi][3], ad);
            }
            uint32_t b[4][4];
#pragma unroll
            for (int p = 0; p < 4; p++) {
                int row = kk * 16 + (lane & 15);
                int col = wn * 64 + p * 16 + ((lane >> 4) << 3);
                uint32_t bd = smem_u32(&sB[row * 136 + col]);
                LDSM4T(b[p][0], b[p][1], b[p][2], b[p][3], bd);
            }
#pragma unroll
            for (int mi = 0; mi < 2; mi++)
#pragma unroll
                for (int nt = 0; nt < 8; nt++)
                    MMA16816(c[mi][nt], a[mi], b[nt >> 1][(nt & 1) * 2],
                             b[nt >> 1][(nt & 1) * 2 + 1]);
        }
    }

    // epilogue: bias + relu (+ con1h store), fused reduction over o
    float pA[8], pB[8];
#pragma unroll
    for (int nt = 0; nt < 8; nt++) { pA[nt] = 0.f; pB[nt] = 0.f; }
#pragma unroll
    for (int mi = 0; mi < 2; mi++) {
        int o0 = bm0 + wm * 32 + mi * 16 + (lane >> 2);
        int o1 = o0 + 8;
        bool gd0 = o0 < Mtot, gd1 = o1 < Mtot;
        float bi0 = gd0 ? __ldg(&bias[o0]) : 0.f;
        float bi1 = gd1 ? __ldg(&bias[o1]) : 0.f;
        float u0 = gd0 ? ((MODE == 0) ? g_u[o0] : __ldg(&F2p[o0])) : 0.f;
        float u1 = gd1 ? ((MODE == 0) ? g_u[o1] : __ldg(&F2p[o1])) : 0.f;
#pragma unroll
        for (int nt = 0; nt < 8; nt++) {
            int gn = n0b + wn * 64 + nt * 8 + (lane & 3) * 2;
            float v00 = fmaxf(c[mi][nt][0] + bi0, 0.f);
            float v01 = fmaxf(c[mi][nt][1] + bi0, 0.f);
            float v10 = fmaxf(c[mi][nt][2] + bi1, 0.f);
            float v11 = fmaxf(c[mi][nt][3] + bi1, 0.f);
            if (MODE == 0) {
                if (gd0) *(__half2*)&g_con1h[(k3 + o0) * Nq + gn] = __floats2half2_rn(v00, v01);
                if (gd1) *(__half2*)&g_con1h[(k3 + o1) * Nq + gn] = __floats2half2_rn(v10, v11);
            }
            pA[nt] = fmaf(v00, u0, fmaf(v10, u1, pA[nt]));
            pB[nt] = fmaf(v01, u0, fmaf(v11, u1, pB[nt]));
        }
    }
#pragma unroll
    for (int nt = 0; nt < 8; nt++) {
#pragma unroll
        for (int off = 4; off < 32; off <<= 1) {
            pA[nt] += __shfl_xor_sync(0xFFFFFFFFu, pA[nt], off);
            pB[nt] += __shfl_xor_sync(0xFFFFFFFFu, pB[nt], off);
        }
    }
    __syncthreads();
    float* red = (float*)sA;   // [4][128]
    if (lane < 4) {
#pragma unroll
        for (int nt = 0; nt < 8; nt++) {
            int cl = wn * 64 + nt * 8 + lane * 2;
            red[wm * 128 + cl] = pA[nt];
            red[wm * 128 + cl + 1] = pB[nt];
        }
    }
    __syncthreads();
    if (tid < 128) {
        float s = red[tid] + red[128 + tid] + red[256 + tid] + red[384 + tid];
        float* dst = (MODE == 0) ? g_qp : g_wdp;
        dst[(blockIdx.z * 10 + blockIdx.y) * Nq + n0b + tid] = s;
    }
}

// ---------------- wdyn: finish fc2.F2, relu, faithful softmax scramble ----------------
__global__ __launch_bounds__(256) void wdyn_kernel(const float* __restrict__ F2,
                                                   const float* __restrict__ b2,
                                                   const float* __restrict__ AngleM) {
    int n = blockIdx.x * 256 + threadIdx.x;
    int t = n >> 9, b = n & 511;
    float wd[10], mx = -1e30f;
#pragma unroll
    for (int k = 0; k < 10; k++) {
        float acc = b2[0] + g_wdp[k * Nq + n] + g_wdp[(10 + k) * Nq + n];
        float fl8 = g_xT[(80 + k) * Nq + n];
        float angv = fabsf(g_xT[(100 + k) * Nq + n] - AngleM[k]) * (1.0f / 360.0f);
        acc = fmaf(fl8, F2[200], fmaf(angv, F2[201], acc));
        wd[k] = fmaxf(acc, 0.f);
        mx = fmaxf(mx, wd[k]);
    }
    float e[10], den = 0.f;
#pragma unroll
    for (int k = 0; k < 10; k++) { e[k] = __expf(wd[k] - mx); den += e[k]; }
    float inv = __fdividef(1.f, den);
#pragma unroll
    for (int k = 0; k < 10; k++) g_sm[t * 5120 + k * 512 + b] = e[k] * inv;
}

// ---------------- final: collapsed linear tail ----------------
__global__ __launch_bounds__(256) void final_kernel(const float* __restrict__ labels,
                                                    const float* __restrict__ a,
                                                    const float* __restrict__ biasout,
                                                    float* __restrict__ out) {
    int n = blockIdx.x * 256 + threadIdx.x;
    int t = n >> 9, b = n & 511;
    float catU = 0.f;
#pragma unroll
    for (int k = 0; k < 10; k++) {
        float q = g_qp[k * Nq + n] + g_qp[(10 + k) * Nq + n] + g_qp[(20 + k) * Nq + n];
        catU = fmaf(q, g_sm[t * 5120 + b * 10 + k], catU);  // faithful flat reshape
    }
    float disU = 0.f;
#pragma unroll
    for (int f = 0; f < 17; f++) {
        float s = 0.f;
#pragma unroll
        for (int k = 0; k < 10; k++) s = fmaf(g_xT[((11 + f) * 10 + k) * Nq + n], g_wA[k], s);
        disU = fmaf(s, g_v[f], disU);
    }
    float aa = a[0];
    float pred = aa * (catU + g_c[0]) + (1.f - aa) * (disU + g_c[1]) + biasout[0];
    out[n] = pred;                    // preds [T,B,1], n = t*B+b
    out[Nq + n] = labels[b * Tq + t]; // labels_r [T,B,1]
}

// ---------------- launch ----------------
extern "C" void kernel_launch(void* const* d_in, const int* in_sizes, int n_in,
                              void* d_out, int out_size) {
    const float* li      = (const float*)d_in[0];
    const float* labels  = (const float*)d_in[1];
    const float* extras  = (const float*)d_in[2];
    const float* DisM    = (const float*)d_in[3];
    const float* AngleM  = (const float*)d_in[4];
    const float* Wih     = (const float*)d_in[5];
    const float* b_ih    = (const float*)d_in[6];
    const float* b_hh    = (const float*)d_in[7];
    const float* Wt      = (const float*)d_in[8];
    const float* bt_ih   = (const float*)d_in[9];
    const float* bt_hh   = (const float*)d_in[10];
    const float* wp      = (const float*)d_in[11];
    const float* bp      = (const float*)d_in[12];
    const float* F1      = (const float*)d_in[13];
    const float* b1      = (const float*)d_in[14];
    const float* F2      = (const float*)d_in[15];
    const float* b2      = (const float*)d_in[16];
    const float* ff      = (const float*)d_in[17];
    const float* bff     = (const float*)d_in[18];
    const float* fuse1   = (const float*)d_in[19];
    const float* biasf   = (const float*)d_in[20];
    const float* Wout    = (const float*)d_in[21];
    const float* biasout = (const float*)d_in[22];
    const float* a       = (const float*)d_in[23];
    float* out = (float*)d_out;

    prep_small<<<1, 320>>>(DisM, fuse1, ff, biasf, bff, Wout);
    prep_Wh<<<(384 * 640 + 256 * 640 + 255) / 256, 256>>>(wp, F1);
    transpose_kernel<<<284 * Nq / 256, 256>>>(li, extras);
    cells_kernel<<<dim3(Nq / 128, 10), 128>>>(Wih, b_ih, b_hh);
    ht_kernel<<<Nq / 128, 128>>>(Wt, bt_ih, bt_hh);
    copy_t0<<<3000 * 512 / 256, 256>>>();
    q_t0_kernel<<<dim3(4, 10), 128>>>();
    mma_gemm<0><<<dim3((Nq - 512) / 128, 10, 3), 256>>>(bp, nullptr);
    mma_gemm<1><<<dim3(Nq / 128, 10, 2), 256>>>(b1, F2);
    wdyn_kernel<<<Nq / 256, 256>>>(F2, b2, AngleM);
    final_kernel<<<Nq / 256, 256>>>(labels, a, biasout, out);
}

// round 13
// speedup vs baseline: 7.1146x; 1.1574x over previous
#include <cuda_runtime.h>
#include <cuda_fp16.h>
#include <cstdint>

#define Bq 512
#define Tq 32
#define Nq 16384   // Tq*Bq, power of two: n = t*512 + b

// ---------------- scratch (static device arrays; no runtime alloc) ----------------
__device__ __align__(16) float  g_xT[280 * Nq];    // [i*10+k][n] transposed local_inputs
__device__ __align__(16) float  g_eT[4 * Nq];      // [i][n] transposed extras
__device__ __align__(16) float  g_con[3000 * 512]; // fp32 con, t=0 columns only (q_t0)
__device__ __align__(16) __half g_conh[3000 * Nq]; // fp16 con (gemm0 B operand)
__device__ __align__(16) __half g_con1h[3000 * Nq];// fp16 con1 (gemm1 B operand)
__device__ __align__(16) __half g_hth[300 * Nq];   // fp16 ht   (gemm1 B operand)
__device__ __align__(16) float  g_sm[Tq * 10 * Bq];// [t][r][c] softmaxed wdyn
__device__ __align__(16) float  g_qp[3 * 10 * Nq]; // per-z partials of con1 . u
__device__ __align__(16) float  g_wdp[2 * 10 * Nq];// per-z partials of relu(fc1) . F2
__device__ __align__(16) float  g_u[300];          // fuse1 @ Wout
__device__ __align__(16) float  g_v[17];           // ff^T @ Wout
__device__ __align__(16) float  g_wA[10];          // softmax(DisM)
__device__ __align__(16) float  g_c[2];            // biasf.Wout, bff.Wout
// zero-padded fp16 weight images: [o][h] row-major, K padded to 640, M padded to 384/256
__device__ __align__(16) __half g_W0h[384 * 640];  // wp   (300x600 live)
__device__ __align__(16) __half g_W1h[256 * 640];  // F1^T (200x600 live)

// ---------------- mma helpers (generic PTX, assembles for plain sm_103) ----------
__device__ __forceinline__ uint32_t smem_u32(const void* p) {
    uint32_t a;
    asm("{ .reg .u64 t; cvta.to.shared.u64 t, %1; cvt.u32.u64 %0, t; }" : "=r"(a) : "l"(p));
    return a;
}
#define LDSM4(r0, r1, r2, r3, addr)                                              \
    asm volatile("ldmatrix.sync.aligned.m8n8.x4.shared.b16 {%0,%1,%2,%3}, [%4];" \
                 : "=r"(r0), "=r"(r1), "=r"(r2), "=r"(r3) : "r"(addr))
#define LDSM4T(r0, r1, r2, r3, addr)                                                   \
    asm volatile("ldmatrix.sync.aligned.m8n8.x4.trans.shared.b16 {%0,%1,%2,%3}, [%4];" \
                 : "=r"(r0), "=r"(r1), "=r"(r2), "=r"(r3) : "r"(addr))
#define MMA16816(c, a, b0, b1)                                                   \
    asm volatile("mma.sync.aligned.m16n8k16.row.col.f32.f16.f16.f32 "            \
                 "{%0,%1,%2,%3}, {%4,%5,%6,%7}, {%8,%9}, {%0,%1,%2,%3};"         \
                 : "+f"((c)[0]), "+f"((c)[1]), "+f"((c)[2]), "+f"((c)[3])        \
                 : "r"((a)[0]), "r"((a)[1]), "r"((a)[2]), "r"((a)[3]),           \
                   "r"(b0), "r"(b1))

// ---------------- math helpers ----------------
__device__ __forceinline__ float tanha(float x) {
    float y;
    asm("tanh.approx.f32 %0, %1;" : "=f"(y) : "f"(x));
    return y;
}
__device__ __forceinline__ float sigm_a(float x) {   // sigmoid via tanh.approx
    return fmaf(0.5f, tanha(0.5f * x), 0.5f);
}
__device__ __forceinline__ float sigm(float x) {     // exact-path sigmoid (prep only)
    float e = __expf(-x);
    return __fdividef(1.f, 1.f + e);
}

// ---------------- prep: tiny precomputations ----------------
__global__ void prep_small(const float* __restrict__ DisM, const float* __restrict__ fuse1,
                           const float* __restrict__ ff, const float* __restrict__ biasf,
                           const float* __restrict__ bff, const float* __restrict__ Wout) {
    int tid = threadIdx.x;
    if (tid < 300) {
        float s = 0.f;
        for (int o = 0; o < 100; o++) s = fmaf(fuse1[tid * 100 + o], Wout[o], s);
        g_u[tid] = s;
    }
    if (tid < 17) {
        float s = 0.f;
        for (int o = 0; o < 100; o++) s = fmaf(ff[o * 17 + tid], Wout[o], s);
        g_v[tid] = s;
    }
    if (tid == 300) {
        float s = 0.f;
        for (int o = 0; o < 100; o++) s = fmaf(biasf[o], Wout[o], s);
        g_c[0] = s;
    }
    if (tid == 301) {
        float s = 0.f;
        for (int o = 0; o < 100; o++) s = fmaf(bff[o], Wout[o], s);
        g_c[1] = s;
    }
    if (tid == 302) {
        float m = DisM[0];
        for (int k = 1; k < 10; k++) m = fmaxf(m, DisM[k]);
        float e[10], d = 0.f;
        for (int k = 0; k < 10; k++) { e[k] = __expf(DisM[k] - m); d += e[k]; }
        for (int k = 0; k < 10; k++) g_wA[k] = e[k] / d;
    }
}

// zero-padded fp16 weight images
__global__ void prep_Wh(const float* __restrict__ wp, const float* __restrict__ F1) {
    int idx = blockIdx.x * 256 + threadIdx.x;
    const int t0 = 384 * 640;
    if (idx < t0) {
        int o = idx / 640, h = idx - o * 640;
        g_W0h[idx] = __float2half_rn((o < 300 && h < 600) ? wp[o * 600 + h] : 0.f);
    } else {
        int j = idx - t0;
        if (j < 256 * 640) {
            int o = j / 640, h = j - o * 640;
            g_W1h[j] = __float2half_rn((o < 200 && h < 600) ? F1[h * 200 + o] : 0.f);
        }
    }
}

// ---------------- transpose inputs to [feature][n] layout ----------------
__global__ void transpose_kernel(const float* __restrict__ li, const float* __restrict__ ex) {
    int idx = blockIdx.x * 256 + threadIdx.x;
    const int total1 = 280 * Nq;
    if (idx < total1) {
        int row = idx >> 14, n = idx & (Nq - 1);
        int i = row / 10, kk = row - i * 10;
        int t = n >> 9, b = n & 511;
        g_xT[idx] = li[((b * Tq + t) * 28 + i) * 10 + kk];
    } else {
        int j = idx - total1;
        if (j < 4 * Nq) {
            int i = j >> 14, n = j & (Nq - 1);
            int t = n >> 9, b = n & 511;
            g_eT[j] = ex[(b * Tq + t) * 4 + i];
        }
    }
}

// ---------------- cells: NV=8 cols/thread, weights staged in smem ----------------
// con = sigm(go) * tanh(sigm(gi) * tanh(gg)); f gate dead.
// Writes g_conh everywhere; g_con (fp32) and g_con1h only for n<512 (t=0 fold-in).
__global__ __launch_bounds__(128) void cells_kernel(const float* __restrict__ Wih,
                                                    const float* __restrict__ b_ih,
                                                    const float* __restrict__ b_hh) {
    __shared__ float sw[300 * 36];   // per j: 11 wi, 11 wg, 11 wo, bi, bg, bo
    const int k = blockIdx.y;
    const int tid = threadIdx.x;
    for (int idx = tid; idx < 10800; idx += 128) {
        int j = idx / 36, r = idx - j * 36;
        float v;
        if (r < 33) {
            int g = r < 11 ? 0 : (r < 22 ? 1 : 2);
            int col = r - g * 11;
            int row = j + (g == 0 ? 0 : (g == 1 ? 600 : 900));
            v = Wih[k * 13200 + row * 11 + col];
        } else {
            int row = j + (r == 33 ? 0 : (r == 34 ? 600 : 900));
            v = b_ih[k * 1200 + row] + b_hh[k * 1200 + row];
        }
        sw[idx] = v;
    }
    __syncthreads();

    const int n0 = blockIdx.x * 1024 + tid * 8;
    float s[11][8];
#pragma unroll
    for (int i = 0; i < 11; i++) {
        float4 v0 = *(const float4*)&g_xT[(i * 10 + k) * Nq + n0];
        float4 v1 = *(const float4*)&g_xT[(i * 10 + k) * Nq + n0 + 4];
        s[i][0] = v0.x; s[i][1] = v0.y; s[i][2] = v0.z; s[i][3] = v0.w;
        s[i][4] = v1.x; s[i][5] = v1.y; s[i][6] = v1.z; s[i][7] = v1.w;
    }
    const bool t0 = (n0 < 512);

    for (int j = 0; j < 300; j++) {
        const float* w = &sw[j * 36];
        float gi[8], gg[8], go[8];
#pragma unroll
        for (int v = 0; v < 8; v++) { gi[v] = w[33]; gg[v] = w[34]; go[v] = w[35]; }
#pragma unroll
        for (int i = 0; i < 11; i++) {
            float wi = w[i], wg = w[11 + i], wo = w[22 + i];
#pragma unroll
            for (int v = 0; v < 8; v++) {
                gi[v] = fmaf(wi, s[i][v], gi[v]);
                gg[v] = fmaf(wg, s[i][v], gg[v]);
                go[v] = fmaf(wo, s[i][v], go[v]);
            }
        }
        float r[8];
#pragma unroll
        for (int v = 0; v < 8; v++)
            r[v] = sigm_a(go[v]) * tanha(sigm_a(gi[v]) * tanha(gg[v]));
        __half2 h2[4];
#pragma unroll
        for (int p = 0; p < 4; p++) h2[p] = __floats2half2_rn(r[2 * p], r[2 * p + 1]);
        const int rowb = (k * 300 + j) * Nq + n0;
        *(uint4*)&g_conh[rowb] = *(uint4*)h2;
        if (t0) {
            *(uint4*)&g_con1h[rowb] = *(uint4*)h2;
            float* cp = &g_con[(k * 300 + j) * 512 + n0];
            *(float4*)&cp[0] = make_float4(r[0], r[1], r[2], r[3]);
            *(float4*)&cp[4] = make_float4(r[4], r[5], r[6], r[7]);
        }
    }
}

// ---------------- target cell: NV=8, weights in smem ----------------
__global__ __launch_bounds__(128) void ht_kernel(const float* __restrict__ Wt,
                                                 const float* __restrict__ bti,
                                                 const float* __restrict__ bth) {
    __shared__ float sw[300 * 15];   // per j: 4 wi, 4 wg, 4 wo, bi, bg, bo
    const int tid = threadIdx.x;
    for (int idx = tid; idx < 4500; idx += 128) {
        int j = idx / 15, r = idx - j * 15;
        float v;
        if (r < 12) {
            int g = r >> 2, col = r & 3;
            int row = j + (g == 0 ? 0 : (g == 1 ? 600 : 900));
            v = Wt[row * 4 + col];
        } else {
            int row = j + (r == 12 ? 0 : (r == 13 ? 600 : 900));
            v = bti[row] + bth[row];
        }
        sw[idx] = v;
    }
    __syncthreads();

    const int n0 = blockIdx.x * 1024 + tid * 8;
    float e[4][8];
#pragma unroll
    for (int i = 0; i < 4; i++) {
        float4 v0 = *(const float4*)&g_eT[i * Nq + n0];
        float4 v1 = *(const float4*)&g_eT[i * Nq + n0 + 4];
        e[i][0] = v0.x; e[i][1] = v0.y; e[i][2] = v0.z; e[i][3] = v0.w;
        e[i][4] = v1.x; e[i][5] = v1.y; e[i][6] = v1.z; e[i][7] = v1.w;
    }
    for (int j = 0; j < 300; j++) {
        const float* w = &sw[j * 15];
        float gi[8], gg[8], go[8];
#pragma unroll
        for (int v = 0; v < 8; v++) { gi[v] = w[12]; gg[v] = w[13]; go[v] = w[14]; }
#pragma unroll
        for (int i = 0; i < 4; i++) {
            float wi = w[i], wg = w[4 + i], wo = w[8 + i];
#pragma unroll
            for (int v = 0; v < 8; v++) {
                gi[v] = fmaf(wi, e[i][v], gi[v]);
                gg[v] = fmaf(wg, e[i][v], gg[v]);
                go[v] = fmaf(wo, e[i][v], go[v]);
            }
        }
        __half2 h2[4];
#pragma unroll
        for (int p = 0; p < 4; p++) {
            float r0 = sigm_a(go[2 * p]) * tanha(sigm_a(gi[2 * p]) * tanha(gg[2 * p]));
            float r1 = sigm_a(go[2 * p + 1]) * tanha(sigm_a(gi[2 * p + 1]) * tanha(gg[2 * p + 1]));
            h2[p] = __floats2half2_rn(r0, r1);
        }
        *(uint4*)&g_hth[j * Nq + n0] = *(uint4*)h2;
    }
}

// q partials for t=0 columns (gemm0 never touches n<512)
__global__ __launch_bounds__(128) void q_t0_kernel() {
    int n = blockIdx.x * 128 + threadIdx.x;   // n < 512
    int k = blockIdx.y;
    const float* cp = g_con + k * 300 * 512 + n;
    float s = 0.f;
#pragma unroll 10
    for (int j = 0; j < 300; j++) s = fmaf(cp[j * 512], g_u[j], s);
    g_qp[k * Nq + n] = s;
    g_qp[(10 + k) * Nq + n] = 0.f;
    g_qp[(20 + k) * Nq + n] = 0.f;
}

// ---------------- tensor-core GEMM (mma.sync m16n8k16 fp16 -> fp32) ----------------
// D[o][n] = sum_h W[o][h] * X[h][n];  CTA tile 128(o) x 128(n), BK=32, K pad 640.
// MODE 0: X = [conh_t ; conh_{t-1}], out con1h = relu(D + bp); partial q = sum_o con1*u
// MODE 1: X = [con1h ; hth], nothing stored but partial wd = sum_o relu(D + b1)*F2
template <int MODE>
__global__ __launch_bounds__(256) void mma_gemm(const float* __restrict__ bias,
                                                const float* __restrict__ F2p) {
    constexpr int Mtot = (MODE == 0) ? 300 : 200;
    __shared__ __align__(16) __half sA[128 * 40];   // [o][k], stride 40
    __shared__ __align__(16) __half sB[32 * 136];   // [k][n], stride 136

    const int tid = threadIdx.x;
    const int lane = tid & 31, wid = tid >> 5;
    const int wm = wid >> 1, wn = wid & 1;          // 4 x 2 warp grid
    const int n0b = (MODE == 0 ? 512 : 0) + blockIdx.x * 128;
    const int k3 = blockIdx.y * 300;
    const int bm0 = blockIdx.z * 128;
    const __half* Wimg = (MODE == 0) ? g_W0h : g_W1h;

    float c[2][8][4];
#pragma unroll
    for (int mi = 0; mi < 2; mi++)
#pragma unroll
        for (int nt = 0; nt < 8; nt++)
#pragma unroll
            for (int e = 0; e < 4; e++) c[mi][nt][e] = 0.f;

    const int arow = tid >> 1, acol = (tid & 1) * 16;   // A: 2 thr/row, 16 halves each
    const int brow = tid >> 3, bcol = (tid & 7) * 16;   // B: 8 thr/row, 16 halves each

    for (int it = 0; it < 20; it++) {
        const int h0 = it * 32;
        uint4 av0 = *(const uint4*)&Wimg[(bm0 + arow) * 640 + h0 + acol];
        uint4 av1 = *(const uint4*)&Wimg[(bm0 + arow) * 640 + h0 + acol + 8];
        uint4 bv0, bv1;
        {
            int h = h0 + brow;
            if (h < 600) {
                const __half* p;
                if (MODE == 0)
                    p = (h < 300) ? &g_conh[(k3 + h) * Nq + n0b + bcol]
                                  : &g_conh[(k3 + h - 300) * Nq + (n0b - 512) + bcol];
                else
                    p = (h < 300) ? &g_con1h[(k3 + h) * Nq + n0b + bcol]
                                  : &g_hth[(h - 300) * Nq + n0b + bcol];
                bv0 = ((const uint4*)p)[0];
                bv1 = ((const uint4*)p)[1];
            } else {
                bv0 = make_uint4(0, 0, 0, 0);
                bv1 = bv0;
            }
        }
        __syncthreads();
        *(uint4*)&sA[arow * 40 + acol] = av0;
        *(uint4*)&sA[arow * 40 + acol + 8] = av1;
        *(uint4*)&sB[brow * 136 + bcol] = bv0;
        *(uint4*)&sB[brow * 136 + bcol + 8] = bv1;
        __syncthreads();

#pragma unroll
        for (int kk = 0; kk < 2; kk++) {
            uint32_t a[2][4];
#pragma unroll
            for (int mi = 0; mi < 2; mi++) {
                int row = wm * 32 + mi * 16 + (lane & 15);
                int col = kk * 16 + ((lane >> 4) << 3);
                uint32_t ad = smem_u32(&sA[row * 40 + col]);
                LDSM4(a[mi][0], a[mi][1], a[mi][2], a[mi][3], ad);
            }
            uint32_t b[4][4];
#pragma unroll
            for (int p = 0; p < 4; p++) {
                int row = kk * 16 + (lane & 15);
                int col = wn * 64 + p * 16 + ((lane >> 4) << 3);
                uint32_t bd = smem_u32(&sB[row * 136 + col]);
                LDSM4T(b[p][0], b[p][1], b[p][2], b[p][3], bd);
            }
#pragma unroll
            for (int mi = 0; mi < 2; mi++)
#pragma unroll
                for (int nt = 0; nt < 8; nt++)
                    MMA16816(c[mi][nt], a[mi], b[nt >> 1][(nt & 1) * 2],
                             b[nt >> 1][(nt & 1) * 2 + 1]);
        }
    }

    // epilogue: bias + relu (+ con1h store), fused reduction over o
    float pA[8], pB[8];
#pragma unroll
    for (int nt = 0; nt < 8; nt++) { pA[nt] = 0.f; pB[nt] = 0.f; }
#pragma unroll
    for (int mi = 0; mi < 2; mi++) {
        int o0 = bm0 + wm * 32 + mi * 16 + (lane >> 2);
        int o1 = o0 + 8;
        bool gd0 = o0 < Mtot, gd1 = o1 < Mtot;
        float bi0 = gd0 ? __ldg(&bias[o0]) : 0.f;
        float bi1 = gd1 ? __ldg(&bias[o1]) : 0.f;
        float u0 = gd0 ? ((MODE == 0) ? g_u[o0] : __ldg(&F2p[o0])) : 0.f;
        float u1 = gd1 ? ((MODE == 0) ? g_u[o1] : __ldg(&F2p[o1])) : 0.f;
#pragma unroll
        for (int nt = 0; nt < 8; nt++) {
            int gn = n0b + wn * 64 + nt * 8 + (lane & 3) * 2;
            float v00 = fmaxf(c[mi][nt][0] + bi0, 0.f);
            float v01 = fmaxf(c[mi][nt][1] + bi0, 0.f);
            float v10 = fmaxf(c[mi][nt][2] + bi1, 0.f);
            float v11 = fmaxf(c[mi][nt][3] + bi1, 0.f);
            if (MODE == 0) {
                if (gd0) *(__half2*)&g_con1h[(k3 + o0) * Nq + gn] = __floats2half2_rn(v00, v01);
                if (gd1) *(__half2*)&g_con1h[(k3 + o1) * Nq + gn] = __floats2half2_rn(v10, v11);
            }
            pA[nt] = fmaf(v00, u0, fmaf(v10, u1, pA[nt]));
            pB[nt] = fmaf(v01, u0, fmaf(v11, u1, pB[nt]));
        }
    }
#pragma unroll
    for (int nt = 0; nt < 8; nt++) {
#pragma unroll
        for (int off = 4; off < 32; off <<= 1) {
            pA[nt] += __shfl_xor_sync(0xFFFFFFFFu, pA[nt], off);
            pB[nt] += __shfl_xor_sync(0xFFFFFFFFu, pB[nt], off);
        }
    }
    __syncthreads();
    float* red = (float*)sA;   // [4][128]
    if (lane < 4) {
#pragma unroll
        for (int nt = 0; nt < 8; nt++) {
            int cl = wn * 64 + nt * 8 + lane * 2;
            red[wm * 128 + cl] = pA[nt];
            red[wm * 128 + cl + 1] = pB[nt];
        }
    }
    __syncthreads();
    if (tid < 128) {
        float s = red[tid] + red[128 + tid] + red[256 + tid] + red[384 + tid];
        float* dst = (MODE == 0) ? g_qp : g_wdp;
        dst[(blockIdx.z * 10 + blockIdx.y) * Nq + n0b + tid] = s;
    }
}

// ---------------- wdyn: finish fc2.F2, relu, faithful softmax scramble ----------------
__global__ __launch_bounds__(256) void wdyn_kernel(const float* __restrict__ F2,
                                                   const float* __restrict__ b2,
                                                   const float* __restrict__ AngleM) {
    int n = blockIdx.x * 256 + threadIdx.x;
    int t = n >> 9, b = n & 511;
    float wd[10], mx = -1e30f;
#pragma unroll
    for (int k = 0; k < 10; k++) {
        float acc = b2[0] + g_wdp[k * Nq + n] + g_wdp[(10 + k) * Nq + n];
        float fl8 = g_xT[(80 + k) * Nq + n];
        float angv = fabsf(g_xT[(100 + k) * Nq + n] - AngleM[k]) * (1.0f / 360.0f);
        acc = fmaf(fl8, F2[200], fmaf(angv, F2[201], acc));
        wd[k] = fmaxf(acc, 0.f);
        mx = fmaxf(mx, wd[k]);
    }
    float e[10], den = 0.f;
#pragma unroll
    for (int k = 0; k < 10; k++) { e[k] = __expf(wd[k] - mx); den += e[k]; }
    float inv = __fdividef(1.f, den);
#pragma unroll
    for (int k = 0; k < 10; k++) g_sm[t * 5120 + k * 512 + b] = e[k] * inv;
}

// ---------------- final: collapsed linear tail ----------------
__global__ __launch_bounds__(256) void final_kernel(const float* __restrict__ labels,
                                                    const float* __restrict__ a,
                                                    const float* __restrict__ biasout,
                                                    float* __restrict__ out) {
    int n = blockIdx.x * 256 + threadIdx.x;
    int t = n >> 9, b = n & 511;
    float catU = 0.f;
#pragma unroll
    for (int k = 0; k < 10; k++) {
        float q = g_qp[k * Nq + n] + g_qp[(10 + k) * Nq + n] + g_qp[(20 + k) * Nq + n];
        catU = fmaf(q, g_sm[t * 5120 + b * 10 + k], catU);  // faithful flat reshape
    }
    float disU = 0.f;
#pragma unroll
    for (int f = 0; f < 17; f++) {
        float s = 0.f;
#pragma unroll
        for (int k = 0; k < 10; k++) s = fmaf(g_xT[((11 + f) * 10 + k) * Nq + n], g_wA[k], s);
        disU = fmaf(s, g_v[f], disU);
    }
    float aa = a[0];
    float pred = aa * (catU + g_c[0]) + (1.f - aa) * (disU + g_c[1]) + biasout[0];
    out[n] = pred;                    // preds [T,B,1], n = t*B+b
    out[Nq + n] = labels[b * Tq + t]; // labels_r [T,B,1]
}

// ---------------- launch ----------------
extern "C" void kernel_launch(void* const* d_in, const int* in_sizes, int n_in,
                              void* d_out, int out_size) {
    const float* li      = (const float*)d_in[0];
    const float* labels  = (const float*)d_in[1];
    const float* extras  = (const float*)d_in[2];
    const float* DisM    = (const float*)d_in[3];
    const float* AngleM  = (const float*)d_in[4];
    const float* Wih     = (const float*)d_in[5];
    const float* b_ih    = (const float*)d_in[6];
    const float* b_hh    = (const float*)d_in[7];
    const float* Wt      = (const float*)d_in[8];
    const float* bt_ih   = (const float*)d_in[9];
    const float* bt_hh   = (const float*)d_in[10];
    const float* wp      = (const float*)d_in[11];
    const float* bp      = (const float*)d_in[12];
    const float* F1      = (const float*)d_in[13];
    const float* b1      = (const float*)d_in[14];
    const float* F2      = (const float*)d_in[15];
    const float* b2      = (const float*)d_in[16];
    const float* ff      = (const float*)d_in[17];
    const float* bff     = (const float*)d_in[18];
    const float* fuse1   = (const float*)d_in[19];
    const float* biasf   = (const float*)d_in[20];
    const float* Wout    = (const float*)d_in[21];
    const float* biasout = (const float*)d_in[22];
    const float* a       = (const float*)d_in[23];
    float* out = (float*)d_out;

    prep_small<<<1, 320>>>(DisM, fuse1, ff, biasf, bff, Wout);
    prep_Wh<<<(384 * 640 + 256 * 640 + 255) / 256, 256>>>(wp, F1);
    transpose_kernel<<<284 * Nq / 256, 256>>>(li, extras);
    cells_kernel<<<dim3(16, 10), 128>>>(Wih, b_ih, b_hh);
    ht_kernel<<<16, 128>>>(Wt, bt_ih, bt_hh);
    q_t0_kernel<<<dim3(4, 10), 128>>>();
    mma_gemm<0><<<dim3((Nq - 512) / 128, 10, 3), 256>>>(bp, nullptr);
    mma_gemm<1><<<dim3(Nq / 128, 10, 2), 256>>>(b1, F2);
    wdyn_kernel<<<Nq / 256, 256>>>(F2, b2, AngleM);
    final_kernel<<<Nq / 256, 256>>>(labels, a, biasout, out);
}

// round 14
// speedup vs baseline: 8.2363x; 1.1577x over previous
#include <cuda_runtime.h>
#include <cuda_fp16.h>
#include <cstdint>

#define Bq 512
#define Tq 32
#define Nq 16384   // Tq*Bq, power of two: n = t*512 + b

// ---------------- scratch (static device arrays; no runtime alloc) ----------------
__device__ __align__(16) float  g_xT[280 * Nq];    // [i*10+k][n] transposed local_inputs
__device__ __align__(16) float  g_eT[4 * Nq];      // [i][n] transposed extras
__device__ __align__(16) float  g_con[3000 * 512]; // fp32 con, t=0 columns only (q_t0)
__device__ __align__(16) __half g_conh[3000 * Nq]; // fp16 con (gemm0 B operand)
__device__ __align__(16) __half g_con1h[3000 * Nq];// fp16 con1 (gemm1 B operand)
__device__ __align__(16) __half g_hth[300 * Nq];   // fp16 ht   (gemm1 B operand)
__device__ __align__(16) float  g_sm[Tq * 10 * Bq];// [t][r][c] softmaxed wdyn
__device__ __align__(16) float  g_qp[3 * 10 * Nq]; // per-z partials of con1 . u
__device__ __align__(16) float  g_wdp[2 * 10 * Nq];// per-z partials of relu(fc1) . F2
__device__ __align__(16) float  g_u[300];          // fuse1 @ Wout
__device__ __align__(16) float  g_v[17];           // ff^T @ Wout
__device__ __align__(16) float  g_wA[10];          // softmax(DisM)
__device__ __align__(16) float  g_c[2];            // biasf.Wout, bff.Wout
// zero-padded fp16 weight images: [o][h] row-major, K padded to 640, M padded to 384/256
__device__ __align__(16) __half g_W0h[384 * 640];  // wp   (300x600 live)
__device__ __align__(16) __half g_W1h[256 * 640];  // F1^T (200x600 live)

// ---------------- mma helpers (generic PTX, assembles for plain sm_103) ----------
__device__ __forceinline__ uint32_t smem_u32(const void* p) {
    uint32_t a;
    asm("{ .reg .u64 t; cvta.to.shared.u64 t, %1; cvt.u32.u64 %0, t; }" : "=r"(a) : "l"(p));
    return a;
}
#define LDSM4(r0, r1, r2, r3, addr)                                              \
    asm volatile("ldmatrix.sync.aligned.m8n8.x4.shared.b16 {%0,%1,%2,%3}, [%4];" \
                 : "=r"(r0), "=r"(r1), "=r"(r2), "=r"(r3) : "r"(addr))
#define LDSM4T(r0, r1, r2, r3, addr)                                                   \
    asm volatile("ldmatrix.sync.aligned.m8n8.x4.trans.shared.b16 {%0,%1,%2,%3}, [%4];" \
                 : "=r"(r0), "=r"(r1), "=r"(r2), "=r"(r3) : "r"(addr))
#define MMA16816(c, a, b0, b1)                                                   \
    asm volatile("mma.sync.aligned.m16n8k16.row.col.f32.f16.f16.f32 "            \
                 "{%0,%1,%2,%3}, {%4,%5,%6,%7}, {%8,%9}, {%0,%1,%2,%3};"         \
                 : "+f"((c)[0]), "+f"((c)[1]), "+f"((c)[2]), "+f"((c)[3])        \
                 : "r"((a)[0]), "r"((a)[1]), "r"((a)[2]), "r"((a)[3]),           \
                   "r"(b0), "r"(b1))

// ---------------- math helpers ----------------
__device__ __forceinline__ float tanha(float x) {
    float y;
    asm("tanh.approx.f32 %0, %1;" : "=f"(y) : "f"(x));
    return y;
}
__device__ __forceinline__ float sigm_a(float x) {   // sigmoid via tanh.approx
    return fmaf(0.5f, tanha(0.5f * x), 0.5f);
}

// ---------------- prep: tiny precomputations ----------------
__global__ void prep_small(const float* __restrict__ DisM, const float* __restrict__ fuse1,
                           const float* __restrict__ ff, const float* __restrict__ biasf,
                           const float* __restrict__ bff, const float* __restrict__ Wout) {
    int tid = threadIdx.x;
    if (tid < 300) {
        float s = 0.f;
        for (int o = 0; o < 100; o++) s = fmaf(fuse1[tid * 100 + o], Wout[o], s);
        g_u[tid] = s;
    }
    if (tid < 17) {
        float s = 0.f;
        for (int o = 0; o < 100; o++) s = fmaf(ff[o * 17 + tid], Wout[o], s);
        g_v[tid] = s;
    }
    if (tid == 300) {
        float s = 0.f;
        for (int o = 0; o < 100; o++) s = fmaf(biasf[o], Wout[o], s);
        g_c[0] = s;
    }
    if (tid == 301) {
        float s = 0.f;
        for (int o = 0; o < 100; o++) s = fmaf(bff[o], Wout[o], s);
        g_c[1] = s;
    }
    if (tid == 302) {
        float m = DisM[0];
        for (int k = 1; k < 10; k++) m = fmaxf(m, DisM[k]);
        float e[10], d = 0.f;
        for (int k = 0; k < 10; k++) { e[k] = __expf(DisM[k] - m); d += e[k]; }
        for (int k = 0; k < 10; k++) g_wA[k] = e[k] / d;
    }
}

// zero-padded fp16 weight images
__global__ void prep_Wh(const float* __restrict__ wp, const float* __restrict__ F1) {
    int idx = blockIdx.x * 256 + threadIdx.x;
    const int t0 = 384 * 640;
    if (idx < t0) {
        int o = idx / 640, h = idx - o * 640;
        g_W0h[idx] = __float2half_rn((o < 300 && h < 600) ? wp[o * 600 + h] : 0.f);
    } else {
        int j = idx - t0;
        if (j < 256 * 640) {
            int o = j / 640, h = j - o * 640;
            g_W1h[j] = __float2half_rn((o < 200 && h < 600) ? F1[h * 200 + o] : 0.f);
        }
    }
}

// ---------------- transpose inputs to [feature][n] layout ----------------
__global__ void transpose_kernel(const float* __restrict__ li, const float* __restrict__ ex) {
    int idx = blockIdx.x * 256 + threadIdx.x;
    const int total1 = 280 * Nq;
    if (idx < total1) {
        int row = idx >> 14, n = idx & (Nq - 1);
        int i = row / 10, kk = row - i * 10;
        int t = n >> 9, b = n & 511;
        g_xT[idx] = li[((b * Tq + t) * 28 + i) * 10 + kk];
    } else {
        int j = idx - total1;
        if (j < 4 * Nq) {
            int i = j >> 14, n = j & (Nq - 1);
            int t = n >> 9, b = n & 511;
            g_eT[j] = ex[(b * Tq + t) * 4 + i];
        }
    }
}

// ---------------- cells: NV=8 cols/thread, j split 3-way across blockIdx.z ------
// con = sigm(go) * tanh(sigm(gi) * tanh(gg)); f gate dead.
// Writes g_conh everywhere; g_con (fp32) and g_con1h only for n<512 (t=0 fold-in).
__global__ __launch_bounds__(128) void cells_kernel(const float* __restrict__ Wih,
                                                    const float* __restrict__ b_ih,
                                                    const float* __restrict__ b_hh) {
    __shared__ float sw[100 * 36];   // per j: 11 wi, 11 wg, 11 wo, bi, bg, bo
    const int k = blockIdx.y;
    const int j0 = blockIdx.z * 100;
    const int tid = threadIdx.x;
    for (int idx = tid; idx < 3600; idx += 128) {
        int j = idx / 36, r = idx - j * 36;
        int jg = j0 + j;
        float v;
        if (r < 33) {
            int g = r < 11 ? 0 : (r < 22 ? 1 : 2);
            int col = r - g * 11;
            int row = jg + (g == 0 ? 0 : (g == 1 ? 600 : 900));
            v = Wih[k * 13200 + row * 11 + col];
        } else {
            int row = jg + (r == 33 ? 0 : (r == 34 ? 600 : 900));
            v = b_ih[k * 1200 + row] + b_hh[k * 1200 + row];
        }
        sw[idx] = v;
    }
    __syncthreads();

    const int n0 = blockIdx.x * 1024 + tid * 8;
    float s[11][8];
#pragma unroll
    for (int i = 0; i < 11; i++) {
        float4 v0 = *(const float4*)&g_xT[(i * 10 + k) * Nq + n0];
        float4 v1 = *(const float4*)&g_xT[(i * 10 + k) * Nq + n0 + 4];
        s[i][0] = v0.x; s[i][1] = v0.y; s[i][2] = v0.z; s[i][3] = v0.w;
        s[i][4] = v1.x; s[i][5] = v1.y; s[i][6] = v1.z; s[i][7] = v1.w;
    }
    const bool t0 = (n0 < 512);

    for (int j = 0; j < 100; j++) {
        const float* w = &sw[j * 36];
        float gi[8], gg[8], go[8];
#pragma unroll
        for (int v = 0; v < 8; v++) { gi[v] = w[33]; gg[v] = w[34]; go[v] = w[35]; }
#pragma unroll
        for (int i = 0; i < 11; i++) {
            float wi = w[i], wg = w[11 + i], wo = w[22 + i];
#pragma unroll
            for (int v = 0; v < 8; v++) {
                gi[v] = fmaf(wi, s[i][v], gi[v]);
                gg[v] = fmaf(wg, s[i][v], gg[v]);
                go[v] = fmaf(wo, s[i][v], go[v]);
            }
        }
        float r[8];
#pragma unroll
        for (int v = 0; v < 8; v++)
            r[v] = sigm_a(go[v]) * tanha(sigm_a(gi[v]) * tanha(gg[v]));
        __half2 h2[4];
#pragma unroll
        for (int p = 0; p < 4; p++) h2[p] = __floats2half2_rn(r[2 * p], r[2 * p + 1]);
        const int jg = j0 + j;
        const int rowb = (k * 300 + jg) * Nq + n0;
        *(uint4*)&g_conh[rowb] = *(uint4*)h2;
        if (t0) {
            *(uint4*)&g_con1h[rowb] = *(uint4*)h2;
            float* cp = &g_con[(k * 300 + jg) * 512 + n0];
            *(float4*)&cp[0] = make_float4(r[0], r[1], r[2], r[3]);
            *(float4*)&cp[4] = make_float4(r[4], r[5], r[6], r[7]);
        }
    }
}

// ---------------- target cell: NV=1, 128 CTAs ----------------
__global__ __launch_bounds__(128) void ht_kernel(const float* __restrict__ Wt,
                                                 const float* __restrict__ bti,
                                                 const float* __restrict__ bth) {
    __shared__ float sw[300 * 15];   // per j: 4 wi, 4 wg, 4 wo, bi, bg, bo
    const int tid = threadIdx.x;
    for (int idx = tid; idx < 4500; idx += 128) {
        int j = idx / 15, r = idx - j * 15;
        float v;
        if (r < 12) {
            int g = r >> 2, col = r & 3;
            int row = j + (g == 0 ? 0 : (g == 1 ? 600 : 900));
            v = Wt[row * 4 + col];
        } else {
            int row = j + (r == 12 ? 0 : (r == 13 ? 600 : 900));
            v = bti[row] + bth[row];
        }
        sw[idx] = v;
    }
    __syncthreads();

    const int n = blockIdx.x * 128 + tid;
    float e0 = g_eT[n], e1 = g_eT[Nq + n], e2 = g_eT[2 * Nq + n], e3 = g_eT[3 * Nq + n];
    for (int j = 0; j < 300; j++) {
        const float* w = &sw[j * 15];
        float gi = fmaf(w[0], e0, fmaf(w[1], e1, fmaf(w[2], e2, fmaf(w[3], e3, w[12]))));
        float gg = fmaf(w[4], e0, fmaf(w[5], e1, fmaf(w[6], e2, fmaf(w[7], e3, w[13]))));
        float go = fmaf(w[8], e0, fmaf(w[9], e1, fmaf(w[10], e2, fmaf(w[11], e3, w[14]))));
        g_hth[j * Nq + n] = __float2half_rn(sigm_a(go) * tanha(sigm_a(gi) * tanha(gg)));
    }
}

// q partials for t=0 columns (gemm0 never touches n<512)
__global__ __launch_bounds__(128) void q_t0_kernel() {
    int n = blockIdx.x * 128 + threadIdx.x;   // n < 512
    int k = blockIdx.y;
    const float* cp = g_con + k * 300 * 512 + n;
    float s = 0.f;
#pragma unroll 10
    for (int j = 0; j < 300; j++) s = fmaf(cp[j * 512], g_u[j], s);
    g_qp[k * Nq + n] = s;
    g_qp[(10 + k) * Nq + n] = 0.f;
    g_qp[(20 + k) * Nq + n] = 0.f;
}

// ---------------- tensor-core GEMM (mma.sync m16n8k16 fp16 -> fp32) ----------------
// D[o][n] = sum_h W[o][h] * X[h][n];  CTA tile 128(o) x 128(n), BK=32, K pad 640.
// MODE 0: X = [conh_t ; conh_{t-1}], out con1h = relu(D + bp); partial q = sum_o con1*u
// MODE 1: X = [con1h ; hth], nothing stored but partial wd = sum_o relu(D + b1)*F2
template <int MODE>
__global__ __launch_bounds__(256) void mma_gemm(const float* __restrict__ bias,
                                                const float* __restrict__ F2p) {
    constexpr int Mtot = (MODE == 0) ? 300 : 200;
    __shared__ __align__(16) __half sA[128 * 40];   // [o][k], stride 40
    __shared__ __align__(16) __half sB[32 * 136];   // [k][n], stride 136

    const int tid = threadIdx.x;
    const int lane = tid & 31, wid = tid >> 5;
    const int wm = wid >> 1, wn = wid & 1;          // 4 x 2 warp grid
    const int n0b = (MODE == 0 ? 512 : 0) + blockIdx.x * 128;
    const int k3 = blockIdx.y * 300;
    const int bm0 = blockIdx.z * 128;
    const __half* Wimg = (MODE == 0) ? g_W0h : g_W1h;

    float c[2][8][4];
#pragma unroll
    for (int mi = 0; mi < 2; mi++)
#pragma unroll
        for (int nt = 0; nt < 8; nt++)
#pragma unroll
            for (int e = 0; e < 4; e++) c[mi][nt][e] = 0.f;

    const int arow = tid >> 1, acol = (tid & 1) * 16;   // A: 2 thr/row, 16 halves each
    const int brow = tid >> 3, bcol = (tid & 7) * 16;   // B: 8 thr/row, 16 halves each

    for (int it = 0; it < 20; it++) {
        const int h0 = it * 32;
        uint4 av0 = *(const uint4*)&Wimg[(bm0 + arow) * 640 + h0 + acol];
        uint4 av1 = *(const uint4*)&Wimg[(bm0 + arow) * 640 + h0 + acol + 8];
        uint4 bv0, bv1;
        {
            int h = h0 + brow;
            if (h < 600) {
                const __half* p;
                if (MODE == 0)
                    p = (h < 300) ? &g_conh[(k3 + h) * Nq + n0b + bcol]
                                  : &g_conh[(k3 + h - 300) * Nq + (n0b - 512) + bcol];
                else
                    p = (h < 300) ? &g_con1h[(k3 + h) * Nq + n0b + bcol]
                                  : &g_hth[(h - 300) * Nq + n0b + bcol];
                bv0 = ((const uint4*)p)[0];
                bv1 = ((const uint4*)p)[1];
            } else {
                bv0 = make_uint4(0, 0, 0, 0);
                bv1 = bv0;
            }
        }
        __syncthreads();
        *(uint4*)&sA[arow * 40 + acol] = av0;
        *(uint4*)&sA[arow * 40 + acol + 8] = av1;
        *(uint4*)&sB[brow * 136 + bcol] = bv0;
        *(uint4*)&sB[brow * 136 + bcol + 8] = bv1;
        __syncthreads();

#pragma unroll
        for (int kk = 0; kk < 2; kk++) {
            uint32_t a[2][4];
#pragma unroll
            for (int mi = 0; mi < 2; mi++) {
                int row = wm * 32 + mi * 16 + (lane & 15);
                int col = kk * 16 + ((lane >> 4) << 3);
                uint32_t ad = smem_u32(&sA[row * 40 + col]);
                LDSM4(a[mi][0], a[mi][1], a[mi][2], a[mi][3], ad);
            }
            uint32_t b[4][4];
#pragma unroll
            for (int p = 0; p < 4; p++) {
                int row = kk * 16 + (lane & 15);
                int col = wn * 64 + p * 16 + ((lane >> 4) << 3);
                uint32_t bd = smem_u32(&sB[row * 136 + col]);
                LDSM4T(b[p][0], b[p][1], b[p][2], b[p][3], bd);
            }
#pragma unroll
            for (int mi = 0; mi < 2; mi++)
#pragma unroll
                for (int nt = 0; nt < 8; nt++)
                    MMA16816(c[mi][nt], a[mi], b[nt >> 1][(nt & 1) * 2],
                             b[nt >> 1][(nt & 1) * 2 + 1]);
        }
    }

    // epilogue: bias + relu (+ con1h store), fused reduction over o
    float pA[8], pB[8];
#pragma unroll
    for (int nt = 0; nt < 8; nt++) { pA[nt] = 0.f; pB[nt] = 0.f; }
#pragma unroll
    for (int mi = 0; mi < 2; mi++) {
        int o0 = bm0 + wm * 32 + mi * 16 + (lane >> 2);
        int o1 = o0 + 8;
        bool gd0 = o0 < Mtot, gd1 = o1 < Mtot;
        float bi0 = gd0 ? __ldg(&bias[o0]) : 0.f;
        float bi1 = gd1 ? __ldg(&bias[o1]) : 0.f;
        float u0 = gd0 ? ((MODE == 0) ? g_u[o0] : __ldg(&F2p[o0])) : 0.f;
        float u1 = gd1 ? ((MODE == 0) ? g_u[o1] : __ldg(&F2p[o1])) : 0.f;
#pragma unroll
        for (int nt = 0; nt < 8; nt++) {
            int gn = n0b + wn * 64 + nt * 8 + (lane & 3) * 2;
            float v00 = fmaxf(c[mi][nt][0] + bi0, 0.f);
            float v01 = fmaxf(c[mi][nt][1] + bi0, 0.f);
            float v10 = fmaxf(c[mi][nt][2] + bi1, 0.f);
            float v11 = fmaxf(c[mi][nt][3] + bi1, 0.f);
            if (MODE == 0) {
                if (gd0) *(__half2*)&g_con1h[(k3 + o0) * Nq + gn] = __floats2half2_rn(v00, v01);
                if (gd1) *(__half2*)&g_con1h[(k3 + o1) * Nq + gn] = __floats2half2_rn(v10, v11);
            }
            pA[nt] = fmaf(v00, u0, fmaf(v10, u1, pA[nt]));
            pB[nt] = fmaf(v01, u0, fmaf(v11, u1, pB[nt]));
        }
    }
#pragma unroll
    for (int nt = 0; nt < 8; nt++) {
#pragma unroll
        for (int off = 4; off < 32; off <<= 1) {
            pA[nt] += __shfl_xor_sync(0xFFFFFFFFu, pA[nt], off);
            pB[nt] += __shfl_xor_sync(0xFFFFFFFFu, pB[nt], off);
        }
    }
    __syncthreads();
    float* red = (float*)sA;   // [4][128]
    if (lane < 4) {
#pragma unroll
        for (int nt = 0; nt < 8; nt++) {
            int cl = wn * 64 + nt * 8 + lane * 2;
            red[wm * 128 + cl] = pA[nt];
            red[wm * 128 + cl + 1] = pB[nt];
        }
    }
    __syncthreads();
    if (tid < 128) {
        float s = red[tid] + red[128 + tid] + red[256 + tid] + red[384 + tid];
        float* dst = (MODE == 0) ? g_qp : g_wdp;
        dst[(blockIdx.z * 10 + blockIdx.y) * Nq + n0b + tid] = s;
    }
}

// ---------------- wdyn: finish fc2.F2, relu, faithful softmax scramble ----------------
__global__ __launch_bounds__(256) void wdyn_kernel(const float* __restrict__ F2,
                                                   const float* __restrict__ b2,
                                                   const float* __restrict__ AngleM) {
    int n = blockIdx.x * 256 + threadIdx.x;
    int t = n >> 9, b = n & 511;
    float wd[10], mx = -1e30f;
#pragma unroll
    for (int k = 0; k < 10; k++) {
        float acc = b2[0] + g_wdp[k * Nq + n] + g_wdp[(10 + k) * Nq + n];
        float fl8 = g_xT[(80 + k) * Nq + n];
        float angv = fabsf(g_xT[(100 + k) * Nq + n] - AngleM[k]) * (1.0f / 360.0f);
        acc = fmaf(fl8, F2[200], fmaf(angv, F2[201], acc));
        wd[k] = fmaxf(acc, 0.f);
        mx = fmaxf(mx, wd[k]);
    }
    float e[10], den = 0.f;
#pragma unroll
    for (int k = 0; k < 10; k++) { e[k] = __expf(wd[k] - mx); den += e[k]; }
    float inv = __fdividef(1.f, den);
#pragma unroll
    for (int k = 0; k < 10; k++) g_sm[t * 5120 + k * 512 + b] = e[k] * inv;
}

// ---------------- final: collapsed linear tail ----------------
__global__ __launch_bounds__(256) void final_kernel(const float* __restrict__ labels,
                                                    const float* __restrict__ a,
                                                    const float* __restrict__ biasout,
                                                    float* __restrict__ out) {
    int n = blockIdx.x * 256 + threadIdx.x;
    int t = n >> 9, b = n & 511;
    float catU = 0.f;
#pragma unroll
    for (int k = 0; k < 10; k++) {
        float q = g_qp[k * Nq + n] + g_qp[(10 + k) * Nq + n] + g_qp[(20 + k) * Nq + n];
        catU = fmaf(q, g_sm[t * 5120 + b * 10 + k], catU);  // faithful flat reshape
    }
    float disU = 0.f;
#pragma unroll
    for (int f = 0; f < 17; f++) {
        float s = 0.f;
#pragma unroll
        for (int k = 0; k < 10; k++) s = fmaf(g_xT[((11 + f) * 10 + k) * Nq + n], g_wA[k], s);
        disU = fmaf(s, g_v[f], disU);
    }
    float aa = a[0];
    float pred = aa * (catU + g_c[0]) + (1.f - aa) * (disU + g_c[1]) + biasout[0];
    out[n] = pred;                    // preds [T,B,1], n = t*B+b
    out[Nq + n] = labels[b * Tq + t]; // labels_r [T,B,1]
}

// ---------------- launch ----------------
extern "C" void kernel_launch(void* const* d_in, const int* in_sizes, int n_in,
                              void* d_out, int out_size) {
    const float* li      = (const float*)d_in[0];
    const float* labels  = (const float*)d_in[1];
    const float* extras  = (const float*)d_in[2];
    const float* DisM    = (const float*)d_in[3];
    const float* AngleM  = (const float*)d_in[4];
    const float* Wih     = (const float*)d_in[5];
    const float* b_ih    = (const float*)d_in[6];
    const float* b_hh    = (const float*)d_in[7];
    const float* Wt      = (const float*)d_in[8];
    const float* bt_ih   = (const float*)d_in[9];
    const float* bt_hh   = (const float*)d_in[10];
    const float* wp      = (const float*)d_in[11];
    const float* bp      = (const float*)d_in[12];
    const float* F1      = (const float*)d_in[13];
    const float* b1      = (const float*)d_in[14];
    const float* F2      = (const float*)d_in[15];
    const float* b2      = (const float*)d_in[16];
    const float* ff      = (const float*)d_in[17];
    const float* bff     = (const float*)d_in[18];
    const float* fuse1   = (const float*)d_in[19];
    const float* biasf   = (const float*)d_in[20];
    const float* Wout    = (const float*)d_in[21];
    const float* biasout = (const float*)d_in[22];
    const float* a       = (const float*)d_in[23];
    float* out = (float*)d_out;

    prep_small<<<1, 320>>>(DisM, fuse1, ff, biasf, bff, Wout);
    prep_Wh<<<(384 * 640 + 256 * 640 + 255) / 256, 256>>>(wp, F1);
    transpose_kernel<<<284 * Nq / 256, 256>>>(li, extras);
    cells_kernel<<<dim3(16, 10, 3), 128>>>(Wih, b_ih, b_hh);
    ht_kernel<<<Nq / 128, 128>>>(Wt, bt_ih, bt_hh);
    q_t0_kernel<<<dim3(4, 10), 128>>>();
    mma_gemm<0><<<dim3((Nq - 512) / 128, 10, 3), 256>>>(bp, nullptr);
    mma_gemm<1><<<dim3(Nq / 128, 10, 2), 256>>>(b1, F2);
    wdyn_kernel<<<Nq / 256, 256>>>(F2, b2, AngleM);
    final_kernel<<<Nq / 256, 256>>>(labels, a, biasout, out);
}